// round 12
// baseline (speedup 1.0000x reference)
#include <cuda_runtime.h>
#include <cuda_fp16.h>
#include <cstdint>
#include <math.h>

// ---------------- problem constants ----------------
#define NSENT 4096
#define MKNOW 4096
#define HEADS 8
#define SENTD 1024
#define HD    128

// ---------------- GEMM tile config ----------------
#define BM 128
#define BN 128
#define BKH 64                          // k halves per stage (4 mma k16 steps)
#define TILE_BYTES_H (128 * 128)        // 128 rows x 128B
#define STAGE_BYTES (2 * TILE_BYTES_H)  // A + B = 32 KB
#define STAGES 3
#define SMEM_BYTES (STAGES * STAGE_BYTES)   // 96 KB -> 2 CTAs/SM

// ---------------- scratch (static device arrays) ----------------
__device__ __half g_sentH[(size_t)NSENT*SENTD];
__device__ __half g_knowH[(size_t)MKNOW*SENTD];
__device__ __half g_WsTh[(size_t)HEADS*HD*SENTD];
__device__ __half g_WkTh[(size_t)HEADS*HD*SENTD];
__device__ __half g_Sh [(size_t)HEADS*NSENT*HD];
__device__ __half g_Kph[(size_t)HEADS*MKNOW*HD];
__device__ __half g_WfTh[(size_t)SENTD*HEADS*SENTD];
__device__ __half g_PTh[(size_t)HEADS*SENTD*MKNOW];     // PT'[h][e][m] = (know @ Wf_h)^T * csinv
__device__ __half g_Eh[(size_t)HEADS*NSENT*MKNOW];      // exp(scores) fp16 perm16, 268MB
__device__ float  g_colsum[HEADS*MKNOW];
__device__ float  g_csinv[HEADS*MKNOW];

// ---------------- helpers ----------------
__device__ __forceinline__ uint32_t smem_u32(const void* p) {
    uint32_t a;
    asm("{ .reg .u64 t; cvta.to.shared.u64 t, %1; cvt.u32.u64 %0, t; }" : "=r"(a) : "l"(p));
    return a;
}
// within-16 K permutation: k = 8b + 2c + r  ->  4c + 2b + r
__device__ __forceinline__ int perm16(int k) {
    return (k & ~15) | (((k >> 1) & 3) << 2) | (((k >> 3) & 1) << 1) | (k & 1);
}

#define CP_ASYNC16(dst, src) \
    asm volatile("cp.async.cg.shared.global [%0], [%1], 16;" :: "r"(dst), "l"(src) : "memory")
#define CP_COMMIT() asm volatile("cp.async.commit_group;" ::: "memory")
#define CP_WAIT1()  asm volatile("cp.async.wait_group 1;" ::: "memory")

#define MMA_F16(d, a0, a1, a2, a3, b0, b1) \
    asm volatile("mma.sync.aligned.m16n8k16.row.col.f32.f16.f16.f32 " \
        "{%0,%1,%2,%3}, {%4,%5,%6,%7}, {%8,%9}, {%0,%1,%2,%3};" \
        : "+f"((d)[0]), "+f"((d)[1]), "+f"((d)[2]), "+f"((d)[3]) \
        : "r"(a0), "r"(a1), "r"(a2), "r"(a3), "r"(b0), "r"(b1))

enum { MODE_BIAS = 1, MODE_SUME = 3, MODE_SCALE = 5, MODE_RED = 7 };

// ---------------- fp16 mma.sync GEMM ----------------
// C[M x N] (+ per-blockIdx.z batch strides) = A[M x K] * B[N x K]^T.
// A, B: __half, stored with the within-16 K permutation (perm16).
// MODE_BIAS  (PR=1): C half perm16 cols, +bias.
// MODE_SUME  (PR=1): C half perm16 = exp(alpha*acc); colsum[h][c] += col sums.
// MODE_SCALE (PR=1): C half perm16 = acc * csinv[h][c]   (colsum arg = csinv).
// MODE_RED   (PR=0): atomicAdd fp32 acc into C (split over blockIdx.z; sC = 0).
template <int MODE, int PR>
__global__ void __launch_bounds__(256, 2)
hgemm_k(const __half* __restrict__ A, const __half* __restrict__ B, void* __restrict__ Cv,
        int Kn, int lda, int ldb, int ldc,
        long long sA, long long sB, long long sC,
        const float* __restrict__ bias, int sBias, float alpha,
        float* __restrict__ colsum, int sCol)
{
    extern __shared__ char smem[];
    const uint32_t smem_b = smem_u32(smem);
    const int h = blockIdx.z;
    A += (long long)h * sA;
    B += (long long)h * sB;

    const int t = threadIdx.x;
    const int wid = t >> 5, lane = t & 31;
    const int lr = lane >> 2;    // 0..7
    const int lc = lane & 3;     // 0..3
    const int wm = (wid & 1) * 64;
    const int wn = (wid >> 1) * 32;
    const int row0 = blockIdx.y * BM;
    const int col0 = blockIdx.x * BN;
    const int nKT = Kn / BKH;

    // fill mapping: per operand 128 rows x 8 chunks(16B); 4 chunks/thread
    // smem slot of chunk o in row r: o ^ ((r&3)<<1)   (conflict-free swizzle)
#define LOAD_TILE(kt, s) do { \
    long long _k0 = (long long)(kt) * BKH; \
    uint32_t _sa = smem_b + (s) * STAGE_BYTES; \
    uint32_t _sb2 = _sa + TILE_BYTES_H; \
    _Pragma("unroll") \
    for (int _q = 0; _q < 4; _q++) { \
        int _ci = t + _q * 256; \
        int _r = _ci >> 3, _o = _ci & 7; \
        uint32_t _d = _r * 128 + (uint32_t)((_o ^ ((_r & 3) << 1)) << 4); \
        CP_ASYNC16(_sa + _d,  A + (long long)(row0 + _r) * lda + _k0 + _o * 8); \
        CP_ASYNC16(_sb2 + _d, B + (long long)(col0 + _r) * ldb + _k0 + _o * 8); \
    } \
} while (0)

    float acc[4][4][4];
#pragma unroll
    for (int i = 0; i < 4; i++)
#pragma unroll
        for (int j = 0; j < 4; j++)
#pragma unroll
            for (int q = 0; q < 4; q++) acc[i][j][q] = 0.0f;

    LOAD_TILE(0, 0); CP_COMMIT();
    LOAD_TILE(1, 1); CP_COMMIT();

    const uint32_t sx = (uint32_t)((lr & 3) << 1);   // row&3 == lr&3 for all fragment rows
    const uint32_t inb = (uint32_t)((lc & 1) * 8);   // byte within 16B chunk
    const uint32_t ch0 = (uint32_t)(lc >> 1);        // chunk within 32B k-group

    int sb = 0;  // = it % 3
    for (int it = 0; it < nKT; it++) {
        CP_WAIT1();
        __syncthreads();
        if (it + 2 < nKT) {
            int sl = sb + 2; if (sl >= STAGES) sl -= STAGES;
            LOAD_TILE(it + 2, sl);
        }
        CP_COMMIT();

        const char* As = smem + sb * STAGE_BYTES;
        const char* Bs = As + TILE_BYTES_H;
#pragma unroll
        for (int ks = 0; ks < 4; ks++) {
            const uint32_t aoff = (((ch0 + 2 * ks) ^ sx) << 4) + inb;
            uint2 al[4], ah[4], b[4];
#pragma unroll
            for (int i = 0; i < 4; i++) {
                const int ra = wm + i * 16 + lr;
                al[i] = *(const uint2*)(As + ra * 128 + aoff);
                ah[i] = *(const uint2*)(As + (ra + 8) * 128 + aoff);
            }
#pragma unroll
            for (int j = 0; j < 4; j++) {
                const int rb = wn + j * 8 + lr;
                b[j] = *(const uint2*)(Bs + rb * 128 + aoff);
            }
#pragma unroll
            for (int i = 0; i < 4; i++)
#pragma unroll
                for (int j = 0; j < 4; j++)
                    MMA_F16(acc[i][j], al[i].x, ah[i].x, al[i].y, ah[i].y, b[j].x, b[j].y);
        }
        sb++; if (sb == STAGES) sb = 0;
    }

    // epilogue
    const long long co = (long long)h * sC;
    float*  Cf = (float*)Cv + co;
    __half* Ch = (__half*)Cv + co;
#pragma unroll
    for (int j = 0; j < 4; j++) {
        const int c = col0 + wn + j * 8 + lc * 2;
        float b0 = 0.0f, b1 = 0.0f;
        if (MODE == MODE_BIAS) {
            b0 = bias[(long long)h * sBias + c];
            b1 = bias[(long long)h * sBias + c + 1];
        }
        float inv0 = 0.0f, inv1 = 0.0f;
        if (MODE == MODE_SCALE) {
            inv0 = colsum[(long long)h * sCol + c];       // csinv
            inv1 = colsum[(long long)h * sCol + c + 1];
        }
        float s0 = 0.0f, s1 = 0.0f;
#pragma unroll
        for (int i = 0; i < 4; i++) {
            const int r = row0 + wm + i * 16 + lr;
            float d0 = acc[i][j][0], d1 = acc[i][j][1];
            float d2 = acc[i][j][2], d3 = acc[i][j][3];
            if (MODE == MODE_SUME) {
                d0 = __expf(d0 * alpha); d1 = __expf(d1 * alpha);
                d2 = __expf(d2 * alpha); d3 = __expf(d3 * alpha);
                s0 += d0 + d2; s1 += d1 + d3;
            } else if (MODE == MODE_SCALE) {
                d0 *= inv0; d1 *= inv1; d2 *= inv0; d3 *= inv1;
            } else if (MODE == MODE_BIAS) {
                d0 += b0; d1 += b1; d2 += b0; d3 += b1;
            }
            if (MODE == MODE_RED) {
                atomicAdd(&Cf[(long long)r * ldc + c],           d0);
                atomicAdd(&Cf[(long long)r * ldc + c + 1],       d1);
                atomicAdd(&Cf[(long long)(r + 8) * ldc + c],     d2);
                atomicAdd(&Cf[(long long)(r + 8) * ldc + c + 1], d3);
            } else {   // PR=1 half perm16 store
                const int pc = perm16(c);   // c even -> perm16(c+1) == pc+1
                *(__half2*)&Ch[(long long)r * ldc + pc] = __floats2half2_rn(d0, d1);
                *(__half2*)&Ch[(long long)(r + 8) * ldc + pc] = __floats2half2_rn(d2, d3);
            }
        }
        if (MODE == MODE_SUME) {
#pragma unroll
            for (int msk = 4; msk <= 16; msk <<= 1) {
                s0 += __shfl_xor_sync(0xFFFFFFFFu, s0, msk);
                s1 += __shfl_xor_sync(0xFFFFFFFFu, s1, msk);
            }
            if (lane < 4) {
                atomicAdd(&colsum[(long long)h * sCol + c], s0);
                atomicAdd(&colsum[(long long)h * sCol + c + 1], s1);
            }
        }
    }
}

// ---------------- prep / softmax kernels ----------------

// fp32 -> fp16 RN, within-16 perm, same layout. total % 16 == 0.
__global__ void converth_k(const float* __restrict__ in, __half* __restrict__ out,
                           long long total) {
    const long long ng = total >> 4;
    for (long long g = (long long)blockIdx.x * blockDim.x + threadIdx.x;
         g < ng; g += (long long)gridDim.x * blockDim.x) {
        const float* p = in + (g << 4);
        __half tmp[16];
#pragma unroll
        for (int j = 0; j < 16; j++) tmp[perm16(j)] = __float2half_rn(p[j]);
        *(uint4*)(out + (g << 4))     = *(uint4*)tmp;
        *(uint4*)(out + (g << 4) + 8) = *(uint4*)(tmp + 8);
    }
}

// fp32 [R,C] (+batch strides) -> half [C,R] RN-rounded, out-col perm16'd
__global__ void transposeh_k(const float* __restrict__ in, __half* __restrict__ out,
                             int R, int C, long long sIn, long long sOut) {
    __shared__ float tile[32][33];
    const int h = blockIdx.z;
    in += (long long)h * sIn;
    out += (long long)h * sOut;
    const int c0 = blockIdx.x * 32, r0 = blockIdx.y * 32;
    const int x = threadIdx.x, y = threadIdx.y;
#pragma unroll
    for (int j = 0; j < 32; j += 8)
        tile[y + j][x] = in[(long long)(r0 + y + j) * C + c0 + x];
    __syncthreads();
#pragma unroll
    for (int j = 0; j < 32; j += 8)
        out[(long long)(c0 + y + j) * R + r0 + perm16(x)] =
            __float2half_rn(tile[x][y + j]);
}

__global__ void zero_colsum_k() {
    int i = blockIdx.x * blockDim.x + threadIdx.x;
    if (i < HEADS * MKNOW) g_colsum[i] = 0.0f;
}

__global__ void csinv_k() {
    int i = blockIdx.x * blockDim.x + threadIdx.x;
    if (i < HEADS * MKNOW) g_csinv[i] = 1.0f / g_colsum[i];
}

// weights output: wout[h][n][m] = fp16(E)[h][n][perm16(m)] * csinv[h][m]
__global__ void normalizeE_k(const __half* __restrict__ E, float* __restrict__ wout) {
    const long long ngroups = (long long)HEADS * NSENT * (MKNOW / 16);
    for (long long g = (long long)blockIdx.x * blockDim.x + threadIdx.x;
         g < ngroups; g += (long long)gridDim.x * blockDim.x) {
        const int grp = (int)(g & (MKNOW / 16 - 1));
        const long long row = g >> 8;            // h*NSENT + n
        const int h = (int)(row >> 12);
        const int m0 = grp * 16;
        const __half* ep = E + row * MKNOW + m0;
        __half e[16];
        *(uint4*)&e[0] = *(const uint4*)ep;
        *(uint4*)&e[8] = *(const uint4*)(ep + 8);
        const float* ci = &g_csinv[h * MKNOW + m0];
        float o[16];
#pragma unroll
        for (int j = 0; j < 16; j++)
            o[j] = __half2float(e[perm16(j)]) * ci[j];
        float* wp = wout + row * MKNOW + m0;
#pragma unroll
        for (int q = 0; q < 4; q++)
            *(float4*)(wp + q * 4) = make_float4(o[q*4], o[q*4+1], o[q*4+2], o[q*4+3]);
    }
}

// out0[n][e] = b_f[e]  (pre-fill before split-K RED accumulation)
__global__ void initout_k(float* __restrict__ out0, const float* __restrict__ bf) {
    int i = blockIdx.x * blockDim.x + threadIdx.x;     // over 1M float4 groups
    if (i < NSENT * SENTD / 4) {
        int e = (i << 2) & (SENTD - 1);
        ((float4*)out0)[i] = *(const float4*)&bf[e];
    }
}

// ---------------- launch ----------------
extern "C" void kernel_launch(void* const* d_in, const int* in_sizes, int n_in,
                              void* d_out, int out_size)
{
    const float* sentences = (const float*)d_in[0];
    const float* knowledge = (const float*)d_in[1];
    const float* W_s = (const float*)d_in[2];
    const float* b_s = (const float*)d_in[3];
    const float* W_k = (const float*)d_in[4];
    const float* b_k = (const float*)d_in[5];
    const float* W_f = (const float*)d_in[6];
    const float* b_f = (const float*)d_in[7];

    float* out0 = (float*)d_out;                        // [4096,1024]
    float* wout = out0 + (long long)NSENT * SENTD;      // [8*4096,4096]

    __half* gSentH = nullptr; cudaGetSymbolAddress((void**)&gSentH, g_sentH);
    __half* gKnowH = nullptr; cudaGetSymbolAddress((void**)&gKnowH, g_knowH);
    __half* gWsT = nullptr;   cudaGetSymbolAddress((void**)&gWsT, g_WsTh);
    __half* gWkT = nullptr;   cudaGetSymbolAddress((void**)&gWkT, g_WkTh);
    __half* gSh = nullptr;    cudaGetSymbolAddress((void**)&gSh, g_Sh);
    __half* gKph = nullptr;   cudaGetSymbolAddress((void**)&gKph, g_Kph);
    __half* gWfT = nullptr;   cudaGetSymbolAddress((void**)&gWfT, g_WfTh);
    __half* gPT = nullptr;    cudaGetSymbolAddress((void**)&gPT, g_PTh);
    __half* gE = nullptr;     cudaGetSymbolAddress((void**)&gE, g_Eh);
    float* gCs = nullptr;     cudaGetSymbolAddress((void**)&gCs, g_colsum);
    float* gCi = nullptr;     cudaGetSymbolAddress((void**)&gCi, g_csinv);

    cudaFuncSetAttribute(hgemm_k<MODE_BIAS, 1>,  cudaFuncAttributeMaxDynamicSharedMemorySize, SMEM_BYTES);
    cudaFuncSetAttribute(hgemm_k<MODE_SUME, 1>,  cudaFuncAttributeMaxDynamicSharedMemorySize, SMEM_BYTES);
    cudaFuncSetAttribute(hgemm_k<MODE_SCALE, 1>, cudaFuncAttributeMaxDynamicSharedMemorySize, SMEM_BYTES);
    cudaFuncSetAttribute(hgemm_k<MODE_RED, 0>,   cudaFuncAttributeMaxDynamicSharedMemorySize, SMEM_BYTES);

    const float inv_sqrt_hd = 0.08838834764831845f;

    // --- prep: fp16 converts + transposes (all K-perm16'd) ---
    converth_k<<<1024, 256>>>(sentences, gSentH, (long long)NSENT * SENTD);
    converth_k<<<1024, 256>>>(knowledge, gKnowH, (long long)MKNOW * SENTD);
    transposeh_k<<<dim3(HD / 32, SENTD / 32, HEADS), dim3(32, 8)>>>(
        W_s, gWsT, SENTD, HD, (long long)SENTD * HD, (long long)HD * SENTD);
    transposeh_k<<<dim3(HD / 32, SENTD / 32, HEADS), dim3(32, 8)>>>(
        W_k, gWkT, SENTD, HD, (long long)SENTD * HD, (long long)HD * SENTD);
    transposeh_k<<<dim3(SENTD / 32, (HEADS * SENTD) / 32, 1), dim3(32, 8)>>>(
        W_f, gWfT, HEADS * SENTD, SENTD, 0LL, 0LL);
    zero_colsum_k<<<(HEADS * MKNOW + 255) / 256, 256>>>();
    initout_k<<<(NSENT * SENTD / 4 + 255) / 256, 256>>>(out0, b_f);

    // --- projections (plain fp16, K=1024) -> fp16 perm16 S / Kp ---
    hgemm_k<MODE_BIAS, 1><<<dim3(1, NSENT / BM, HEADS), 256, SMEM_BYTES>>>(
        gSentH, gWsT, gSh, SENTD, SENTD, SENTD, HD,
        0LL, (long long)HD * SENTD, (long long)NSENT * HD, b_s, HD, 0.0f, nullptr, 0);
    hgemm_k<MODE_BIAS, 1><<<dim3(1, MKNOW / BM, HEADS), 256, SMEM_BYTES>>>(
        gKnowH, gWkT, gKph, SENTD, SENTD, SENTD, HD,
        0LL, (long long)HD * SENTD, (long long)MKNOW * HD, b_k, HD, 0.0f, nullptr, 0);

    // --- scores (K=128): E = exp(scores/sqrt(HD)) fp16 perm16 + fused colsum ---
    hgemm_k<MODE_SUME, 1><<<dim3(MKNOW / BN, NSENT / BM, HEADS), 256, SMEM_BYTES>>>(
        gSh, gKph, gE, HD, HD, HD, MKNOW,
        (long long)NSENT * HD, (long long)MKNOW * HD, (long long)NSENT * MKNOW,
        nullptr, 0, inv_sqrt_hd, gCs, MKNOW);

    // --- reciprocal column sums ---
    csinv_k<<<(HEADS * MKNOW + 255) / 256, 256>>>();

    // --- PT'[h][e][m] = (sum_d Wf[h*1024+d][e] * know[m][d]) * csinv[h][m] ---
    hgemm_k<MODE_SCALE, 1><<<dim3(MKNOW / BN, SENTD / BM, HEADS), 256, SMEM_BYTES>>>(
        gWfT, gKnowH, gPT, SENTD, HEADS * SENTD, SENTD, MKNOW,
        (long long)SENTD, 0LL, (long long)SENTD * MKNOW, nullptr, 0, 0.0f, gCi, MKNOW);

    // --- weights output: wout = fp16(E) * csinv (pure memory pass) ---
    normalizeE_k<<<8192, 256>>>(gE, wout);

    // --- output: out0 += E[h] @ PT'[h]^T per head (split-K RED, bias pre-filled) ---
    hgemm_k<MODE_RED, 0><<<dim3(SENTD / BN, NSENT / BM, HEADS), 256, SMEM_BYTES>>>(
        gE, gPT, out0, MKNOW, MKNOW, MKNOW, SENTD,
        (long long)NSENT * MKNOW, (long long)SENTD * MKNOW, 0LL,
        nullptr, 0, 0.0f, nullptr, 0);
}

// round 13
// speedup vs baseline: 1.1643x; 1.1643x over previous
#include <cuda_runtime.h>
#include <cuda_fp16.h>
#include <cstdint>
#include <math.h>

// ---------------- problem constants ----------------
#define NSENT 4096
#define MKNOW 4096
#define HEADS 8
#define SENTD 1024
#define HD    128

// ---------------- GEMM tile config ----------------
#define BM 128
#define BN 128
#define BKH 64                          // k halves per stage (4 mma k16 steps)
#define TILE_BYTES_H (128 * 128)        // 128 rows x 128B
#define STAGE_BYTES (2 * TILE_BYTES_H)  // A + B = 32 KB
#define STAGES 3
#define SMEM_BYTES (STAGES * STAGE_BYTES)   // 96 KB -> 2 CTAs/SM

// ---------------- scratch (static device arrays) ----------------
__device__ __half g_sentH[(size_t)NSENT*SENTD];
__device__ __half g_knowH[(size_t)MKNOW*SENTD];
__device__ __half g_WsTh[(size_t)HEADS*HD*SENTD];
__device__ __half g_WkTh[(size_t)HEADS*HD*SENTD];
__device__ __half g_Sh [(size_t)HEADS*NSENT*HD];
__device__ __half g_Kph[(size_t)HEADS*MKNOW*HD];
__device__ __half g_WfTh[(size_t)SENTD*HEADS*SENTD];
__device__ __half g_PTh[(size_t)HEADS*SENTD*MKNOW];     // PT'[h][e][m] = (know @ Wf_h)^T * csinv
__device__ __half g_Eh[(size_t)HEADS*NSENT*MKNOW];      // exp(scores) fp16 perm16, 268MB
__device__ float  g_colsum[HEADS*MKNOW];
__device__ float  g_csinv[HEADS*MKNOW];

// ---------------- helpers ----------------
__device__ __forceinline__ uint32_t smem_u32(const void* p) {
    uint32_t a;
    asm("{ .reg .u64 t; cvta.to.shared.u64 t, %1; cvt.u32.u64 %0, t; }" : "=r"(a) : "l"(p));
    return a;
}
// within-16 K permutation: k = 8b + 2c + r  ->  4c + 2b + r
__device__ __forceinline__ int perm16(int k) {
    return (k & ~15) | (((k >> 1) & 3) << 2) | (((k >> 3) & 1) << 1) | (k & 1);
}

#define CP_ASYNC16(dst, src) \
    asm volatile("cp.async.cg.shared.global [%0], [%1], 16;" :: "r"(dst), "l"(src) : "memory")
#define CP_COMMIT() asm volatile("cp.async.commit_group;" ::: "memory")
#define CP_WAIT1()  asm volatile("cp.async.wait_group 1;" ::: "memory")

#define MMA_F16(d, a0, a1, a2, a3, b0, b1) \
    asm volatile("mma.sync.aligned.m16n8k16.row.col.f32.f16.f16.f32 " \
        "{%0,%1,%2,%3}, {%4,%5,%6,%7}, {%8,%9}, {%0,%1,%2,%3};" \
        : "+f"((d)[0]), "+f"((d)[1]), "+f"((d)[2]), "+f"((d)[3]) \
        : "r"(a0), "r"(a1), "r"(a2), "r"(a3), "r"(b0), "r"(b1))

enum { MODE_BIAS = 1, MODE_SUME = 3, MODE_SCALE = 5, MODE_RED = 7 };

// ---------------- fp16 mma.sync GEMM ----------------
// C[M x N] (+ per-blockIdx.z batch strides) = A[M x K] * B[N x K]^T.
// A, B: __half, stored with the within-16 K permutation (perm16).
// MODE_BIAS  (PR=1): C half perm16 cols, +bias.
// MODE_SUME  (PR=1): C half perm16 = exp(alpha*acc); colsum[h][c] += col sums.
// MODE_SCALE (PR=1): C half perm16 = acc * csinv[h][c]   (colsum arg = csinv).
// MODE_RED   (PR=0): atomicAdd fp32 acc into C (split over blockIdx.z; sC = 0).
//            Additionally (wv != null): prologue writes the CTA's disjoint
//            wout strip wv[(h*NSENT+row)*MKNOW + m] = half(A[row][m]) * csinv[h][m]
//            for m in [blockIdx.x*512, +512), rows row0..row0+127.
template <int MODE, int PR>
__global__ void __launch_bounds__(256, 2)
hgemm_k(const __half* __restrict__ A, const __half* __restrict__ B, void* __restrict__ Cv,
        int Kn, int lda, int ldb, int ldc,
        long long sA, long long sB, long long sC,
        const float* __restrict__ bias, int sBias, float alpha,
        float* __restrict__ colsum, int sCol, float* __restrict__ wv)
{
    extern __shared__ char smem[];
    const uint32_t smem_b = smem_u32(smem);
    const int h = blockIdx.z;
    A += (long long)h * sA;
    B += (long long)h * sB;

    const int t = threadIdx.x;
    const int wid = t >> 5, lane = t & 31;
    const int lr = lane >> 2;    // 0..7
    const int lc = lane & 3;     // 0..3
    const int wm = (wid & 1) * 64;
    const int wn = (wid >> 1) * 32;
    const int row0 = blockIdx.y * BM;
    const int col0 = blockIdx.x * BN;
    const int nKT = Kn / BKH;

    // fill mapping: per operand 128 rows x 8 chunks(16B); 4 chunks/thread
    // smem slot of chunk o in row r: o ^ ((r&3)<<1)   (conflict-free swizzle)
#define LOAD_TILE(kt, s) do { \
    long long _k0 = (long long)(kt) * BKH; \
    uint32_t _sa = smem_b + (s) * STAGE_BYTES; \
    uint32_t _sb2 = _sa + TILE_BYTES_H; \
    _Pragma("unroll") \
    for (int _q = 0; _q < 4; _q++) { \
        int _ci = t + _q * 256; \
        int _r = _ci >> 3, _o = _ci & 7; \
        uint32_t _d = _r * 128 + (uint32_t)((_o ^ ((_r & 3) << 1)) << 4); \
        CP_ASYNC16(_sa + _d,  A + (long long)(row0 + _r) * lda + _k0 + _o * 8); \
        CP_ASYNC16(_sb2 + _d, B + (long long)(col0 + _r) * ldb + _k0 + _o * 8); \
    } \
} while (0)

    float acc[4][4][4];
#pragma unroll
    for (int i = 0; i < 4; i++)
#pragma unroll
        for (int j = 0; j < 4; j++)
#pragma unroll
            for (int q = 0; q < 4; q++) acc[i][j][q] = 0.0f;

    LOAD_TILE(0, 0); CP_COMMIT();
    LOAD_TILE(1, 1); CP_COMMIT();

    // ---- fused weights-output writer (RED only): overlaps with cp.async fill ----
    if (MODE == MODE_RED && wv != nullptr) {
        const int m0 = col0 * 4;                 // x-tile covers 512 m's
        const float* ci = colsum + (long long)h * sCol + m0;
        float* wbase = wv + ((long long)h * NSENT + row0) * MKNOW + m0;
#pragma unroll 1
        for (int g = 0; g < 16; g++) {
            const int idx = (g << 8) + t;        // 0..4095
            const int r = idx >> 5;              // row 0..127
            const int gr = (idx & 31) << 4;      // m offset within strip: 0,16,..,496
            const __half* ep = A + (long long)(row0 + r) * lda + m0 + gr;
            __half e[16];
            *(uint4*)&e[0] = *(const uint4*)ep;
            *(uint4*)&e[8] = *(const uint4*)(ep + 8);
            float ci4[16];
#pragma unroll
            for (int q = 0; q < 4; q++)
                *(float4*)&ci4[q * 4] = *(const float4*)(ci + gr + q * 4);
            float o[16];
#pragma unroll
            for (int j2 = 0; j2 < 16; j2++)
                o[j2] = __half2float(e[perm16(j2)]) * ci4[j2];
            float* wp = wbase + (long long)r * MKNOW + gr;
#pragma unroll
            for (int q = 0; q < 4; q++)
                __stcs((float4*)(wp + q * 4),
                       make_float4(o[q*4], o[q*4+1], o[q*4+2], o[q*4+3]));
        }
    }

    const uint32_t sx = (uint32_t)((lr & 3) << 1);   // row&3 == lr&3 for all fragment rows
    const uint32_t inb = (uint32_t)((lc & 1) * 8);   // byte within 16B chunk
    const uint32_t ch0 = (uint32_t)(lc >> 1);        // chunk within 32B k-group

    int sb = 0;  // = it % 3
    for (int it = 0; it < nKT; it++) {
        CP_WAIT1();
        __syncthreads();
        if (it + 2 < nKT) {
            int sl = sb + 2; if (sl >= STAGES) sl -= STAGES;
            LOAD_TILE(it + 2, sl);
        }
        CP_COMMIT();

        const char* As = smem + sb * STAGE_BYTES;
        const char* Bs = As + TILE_BYTES_H;
#pragma unroll
        for (int ks = 0; ks < 4; ks++) {
            const uint32_t aoff = (((ch0 + 2 * ks) ^ sx) << 4) + inb;
            uint2 al[4], ah[4], b[4];
#pragma unroll
            for (int i = 0; i < 4; i++) {
                const int ra = wm + i * 16 + lr;
                al[i] = *(const uint2*)(As + ra * 128 + aoff);
                ah[i] = *(const uint2*)(As + (ra + 8) * 128 + aoff);
            }
#pragma unroll
            for (int j = 0; j < 4; j++) {
                const int rb = wn + j * 8 + lr;
                b[j] = *(const uint2*)(Bs + rb * 128 + aoff);
            }
#pragma unroll
            for (int i = 0; i < 4; i++)
#pragma unroll
                for (int j = 0; j < 4; j++)
                    MMA_F16(acc[i][j], al[i].x, ah[i].x, al[i].y, ah[i].y, b[j].x, b[j].y);
        }
        sb++; if (sb == STAGES) sb = 0;
    }

    // epilogue
    const long long co = (long long)h * sC;
    float*  Cf = (float*)Cv + co;
    __half* Ch = (__half*)Cv + co;
#pragma unroll
    for (int j = 0; j < 4; j++) {
        const int c = col0 + wn + j * 8 + lc * 2;
        float b0 = 0.0f, b1 = 0.0f;
        if (MODE == MODE_BIAS) {
            b0 = bias[(long long)h * sBias + c];
            b1 = bias[(long long)h * sBias + c + 1];
        }
        float inv0 = 0.0f, inv1 = 0.0f;
        if (MODE == MODE_SCALE) {
            inv0 = colsum[(long long)h * sCol + c];       // csinv
            inv1 = colsum[(long long)h * sCol + c + 1];
        }
        float s0 = 0.0f, s1 = 0.0f;
#pragma unroll
        for (int i = 0; i < 4; i++) {
            const int r = row0 + wm + i * 16 + lr;
            float d0 = acc[i][j][0], d1 = acc[i][j][1];
            float d2 = acc[i][j][2], d3 = acc[i][j][3];
            if (MODE == MODE_SUME) {
                d0 = __expf(d0 * alpha); d1 = __expf(d1 * alpha);
                d2 = __expf(d2 * alpha); d3 = __expf(d3 * alpha);
                s0 += d0 + d2; s1 += d1 + d3;
            } else if (MODE == MODE_SCALE) {
                d0 *= inv0; d1 *= inv1; d2 *= inv0; d3 *= inv1;
            } else if (MODE == MODE_BIAS) {
                d0 += b0; d1 += b1; d2 += b0; d3 += b1;
            }
            if (MODE == MODE_RED) {
                atomicAdd(&Cf[(long long)r * ldc + c],           d0);
                atomicAdd(&Cf[(long long)r * ldc + c + 1],       d1);
                atomicAdd(&Cf[(long long)(r + 8) * ldc + c],     d2);
                atomicAdd(&Cf[(long long)(r + 8) * ldc + c + 1], d3);
            } else {   // PR=1 half perm16 store
                const int pc = perm16(c);   // c even -> perm16(c+1) == pc+1
                *(__half2*)&Ch[(long long)r * ldc + pc] = __floats2half2_rn(d0, d1);
                *(__half2*)&Ch[(long long)(r + 8) * ldc + pc] = __floats2half2_rn(d2, d3);
            }
        }
        if (MODE == MODE_SUME) {
#pragma unroll
            for (int msk = 4; msk <= 16; msk <<= 1) {
                s0 += __shfl_xor_sync(0xFFFFFFFFu, s0, msk);
                s1 += __shfl_xor_sync(0xFFFFFFFFu, s1, msk);
            }
            if (lane < 4) {
                atomicAdd(&colsum[(long long)h * sCol + c], s0);
                atomicAdd(&colsum[(long long)h * sCol + c + 1], s1);
            }
        }
    }
}

// ---------------- prep / softmax kernels ----------------

// fp32 -> fp16 RN, within-16 perm, same layout. total % 16 == 0.
__global__ void converth_k(const float* __restrict__ in, __half* __restrict__ out,
                           long long total) {
    const long long ng = total >> 4;
    for (long long g = (long long)blockIdx.x * blockDim.x + threadIdx.x;
         g < ng; g += (long long)gridDim.x * blockDim.x) {
        const float* p = in + (g << 4);
        __half tmp[16];
#pragma unroll
        for (int j = 0; j < 16; j++) tmp[perm16(j)] = __float2half_rn(p[j]);
        *(uint4*)(out + (g << 4))     = *(uint4*)tmp;
        *(uint4*)(out + (g << 4) + 8) = *(uint4*)(tmp + 8);
    }
}

// fp32 [R,C] (+batch strides) -> half [C,R] RN-rounded, out-col perm16'd
__global__ void transposeh_k(const float* __restrict__ in, __half* __restrict__ out,
                             int R, int C, long long sIn, long long sOut) {
    __shared__ float tile[32][33];
    const int h = blockIdx.z;
    in += (long long)h * sIn;
    out += (long long)h * sOut;
    const int c0 = blockIdx.x * 32, r0 = blockIdx.y * 32;
    const int x = threadIdx.x, y = threadIdx.y;
#pragma unroll
    for (int j = 0; j < 32; j += 8)
        tile[y + j][x] = in[(long long)(r0 + y + j) * C + c0 + x];
    __syncthreads();
#pragma unroll
    for (int j = 0; j < 32; j += 8)
        out[(long long)(c0 + y + j) * R + r0 + perm16(x)] =
            __float2half_rn(tile[x][y + j]);
}

__global__ void zero_colsum_k() {
    int i = blockIdx.x * blockDim.x + threadIdx.x;
    if (i < HEADS * MKNOW) g_colsum[i] = 0.0f;
}

__global__ void csinv_k() {
    int i = blockIdx.x * blockDim.x + threadIdx.x;
    if (i < HEADS * MKNOW) g_csinv[i] = 1.0f / g_colsum[i];
}

// out0[n][e] = b_f[e]  (pre-fill before split-K RED accumulation)
__global__ void initout_k(float* __restrict__ out0, const float* __restrict__ bf) {
    int i = blockIdx.x * blockDim.x + threadIdx.x;     // over 1M float4 groups
    if (i < NSENT * SENTD / 4) {
        int e = (i << 2) & (SENTD - 1);
        ((float4*)out0)[i] = *(const float4*)&bf[e];
    }
}

// ---------------- launch ----------------
extern "C" void kernel_launch(void* const* d_in, const int* in_sizes, int n_in,
                              void* d_out, int out_size)
{
    const float* sentences = (const float*)d_in[0];
    const float* knowledge = (const float*)d_in[1];
    const float* W_s = (const float*)d_in[2];
    const float* b_s = (const float*)d_in[3];
    const float* W_k = (const float*)d_in[4];
    const float* b_k = (const float*)d_in[5];
    const float* W_f = (const float*)d_in[6];
    const float* b_f = (const float*)d_in[7];

    float* out0 = (float*)d_out;                        // [4096,1024]
    float* wout = out0 + (long long)NSENT * SENTD;      // [8*4096,4096]

    __half* gSentH = nullptr; cudaGetSymbolAddress((void**)&gSentH, g_sentH);
    __half* gKnowH = nullptr; cudaGetSymbolAddress((void**)&gKnowH, g_knowH);
    __half* gWsT = nullptr;   cudaGetSymbolAddress((void**)&gWsT, g_WsTh);
    __half* gWkT = nullptr;   cudaGetSymbolAddress((void**)&gWkT, g_WkTh);
    __half* gSh = nullptr;    cudaGetSymbolAddress((void**)&gSh, g_Sh);
    __half* gKph = nullptr;   cudaGetSymbolAddress((void**)&gKph, g_Kph);
    __half* gWfT = nullptr;   cudaGetSymbolAddress((void**)&gWfT, g_WfTh);
    __half* gPT = nullptr;    cudaGetSymbolAddress((void**)&gPT, g_PTh);
    __half* gE = nullptr;     cudaGetSymbolAddress((void**)&gE, g_Eh);
    float* gCs = nullptr;     cudaGetSymbolAddress((void**)&gCs, g_colsum);
    float* gCi = nullptr;     cudaGetSymbolAddress((void**)&gCi, g_csinv);

    cudaFuncSetAttribute(hgemm_k<MODE_BIAS, 1>,  cudaFuncAttributeMaxDynamicSharedMemorySize, SMEM_BYTES);
    cudaFuncSetAttribute(hgemm_k<MODE_SUME, 1>,  cudaFuncAttributeMaxDynamicSharedMemorySize, SMEM_BYTES);
    cudaFuncSetAttribute(hgemm_k<MODE_SCALE, 1>, cudaFuncAttributeMaxDynamicSharedMemorySize, SMEM_BYTES);
    cudaFuncSetAttribute(hgemm_k<MODE_RED, 0>,   cudaFuncAttributeMaxDynamicSharedMemorySize, SMEM_BYTES);

    const float inv_sqrt_hd = 0.08838834764831845f;

    // --- prep: fp16 converts + transposes (all K-perm16'd) ---
    converth_k<<<1024, 256>>>(sentences, gSentH, (long long)NSENT * SENTD);
    converth_k<<<1024, 256>>>(knowledge, gKnowH, (long long)MKNOW * SENTD);
    transposeh_k<<<dim3(HD / 32, SENTD / 32, HEADS), dim3(32, 8)>>>(
        W_s, gWsT, SENTD, HD, (long long)SENTD * HD, (long long)HD * SENTD);
    transposeh_k<<<dim3(HD / 32, SENTD / 32, HEADS), dim3(32, 8)>>>(
        W_k, gWkT, SENTD, HD, (long long)SENTD * HD, (long long)HD * SENTD);
    transposeh_k<<<dim3(SENTD / 32, (HEADS * SENTD) / 32, 1), dim3(32, 8)>>>(
        W_f, gWfT, HEADS * SENTD, SENTD, 0LL, 0LL);
    zero_colsum_k<<<(HEADS * MKNOW + 255) / 256, 256>>>();
    initout_k<<<(NSENT * SENTD / 4 + 255) / 256, 256>>>(out0, b_f);

    // --- projections (plain fp16, K=1024) -> fp16 perm16 S / Kp ---
    hgemm_k<MODE_BIAS, 1><<<dim3(1, NSENT / BM, HEADS), 256, SMEM_BYTES>>>(
        gSentH, gWsT, gSh, SENTD, SENTD, SENTD, HD,
        0LL, (long long)HD * SENTD, (long long)NSENT * HD, b_s, HD, 0.0f, nullptr, 0, nullptr);
    hgemm_k<MODE_BIAS, 1><<<dim3(1, MKNOW / BM, HEADS), 256, SMEM_BYTES>>>(
        gKnowH, gWkT, gKph, SENTD, SENTD, SENTD, HD,
        0LL, (long long)HD * SENTD, (long long)MKNOW * HD, b_k, HD, 0.0f, nullptr, 0, nullptr);

    // --- scores (K=128): E = exp(scores/sqrt(HD)) fp16 perm16 + fused colsum ---
    hgemm_k<MODE_SUME, 1><<<dim3(MKNOW / BN, NSENT / BM, HEADS), 256, SMEM_BYTES>>>(
        gSh, gKph, gE, HD, HD, HD, MKNOW,
        (long long)NSENT * HD, (long long)MKNOW * HD, (long long)NSENT * MKNOW,
        nullptr, 0, inv_sqrt_hd, gCs, MKNOW, nullptr);

    // --- reciprocal column sums ---
    csinv_k<<<(HEADS * MKNOW + 255) / 256, 256>>>();

    // --- PT'[h][e][m] = (sum_d Wf[h*1024+d][e] * know[m][d]) * csinv[h][m] ---
    hgemm_k<MODE_SCALE, 1><<<dim3(MKNOW / BN, SENTD / BM, HEADS), 256, SMEM_BYTES>>>(
        gWfT, gKnowH, gPT, SENTD, HEADS * SENTD, SENTD, MKNOW,
        (long long)SENTD, 0LL, (long long)SENTD * MKNOW, nullptr, 0, 0.0f, gCi, MKNOW, nullptr);

    // --- output: out0 += E[h] @ PT'[h]^T (split-K RED, bias pre-filled);
    //     fused prologue writes wout = fp16(E) * csinv, one disjoint strip per CTA ---
    hgemm_k<MODE_RED, 0><<<dim3(SENTD / BN, NSENT / BM, HEADS), 256, SMEM_BYTES>>>(
        gE, gPT, out0, MKNOW, MKNOW, MKNOW, SENTD,
        (long long)NSENT * MKNOW, (long long)SENTD * MKNOW, 0LL,
        nullptr, 0, 0.0f, gCi, MKNOW, wout);
}

// round 14
// speedup vs baseline: 1.1660x; 1.0015x over previous
#include <cuda_runtime.h>
#include <cuda_fp16.h>
#include <cstdint>
#include <math.h>

// ---------------- problem constants ----------------
#define NSENT 4096
#define MKNOW 4096
#define HEADS 8
#define SENTD 1024
#define HD    128

// ---------------- GEMM tile config ----------------
#define BM 128
#define BN 128
#define BKH 64                          // k halves per stage (4 mma k16 steps)
#define TILE_BYTES_H (128 * 128)        // 128 rows x 128B
#define STAGE_BYTES (2 * TILE_BYTES_H)  // A + B = 32 KB
#define STAGES 3
#define SMEM_BYTES (STAGES * STAGE_BYTES)   // 96 KB -> 2 CTAs/SM

// ---------------- scratch (static device arrays) ----------------
__device__ __half g_sentH[(size_t)NSENT*SENTD];
__device__ __half g_knowH[(size_t)MKNOW*SENTD];
__device__ __half g_WsTh[(size_t)HEADS*HD*SENTD];
__device__ __half g_WkTh[(size_t)HEADS*HD*SENTD];
__device__ __half g_Sh [(size_t)HEADS*NSENT*HD];
__device__ __half g_Kph[(size_t)HEADS*MKNOW*HD];
__device__ __half g_WfTh[(size_t)SENTD*HEADS*SENTD];
__device__ __half g_PTh[(size_t)HEADS*SENTD*MKNOW];     // PT'[h][e][m] = (know @ Wf_h)^T * csinv
__device__ __half g_Eh[(size_t)HEADS*NSENT*MKNOW];      // exp(scores) fp16 perm16, 268MB
__device__ float  g_colsum[HEADS*MKNOW];
__device__ float  g_csinv[HEADS*MKNOW];

// ---------------- helpers ----------------
__device__ __forceinline__ uint32_t smem_u32(const void* p) {
    uint32_t a;
    asm("{ .reg .u64 t; cvta.to.shared.u64 t, %1; cvt.u32.u64 %0, t; }" : "=r"(a) : "l"(p));
    return a;
}
// within-16 K permutation: k = 8b + 2c + r  ->  4c + 2b + r
__device__ __forceinline__ int perm16(int k) {
    return (k & ~15) | (((k >> 1) & 3) << 2) | (((k >> 3) & 1) << 1) | (k & 1);
}
// streaming (evict-first) store of a half2
__device__ __forceinline__ void stcs_h2(__half* p, __half2 v) {
    uint32_t u = *reinterpret_cast<uint32_t*>(&v);
    asm volatile("st.global.cs.b32 [%0], %1;" :: "l"(p), "r"(u) : "memory");
}

#define CP_ASYNC16(dst, src) \
    asm volatile("cp.async.cg.shared.global [%0], [%1], 16;" :: "r"(dst), "l"(src) : "memory")
#define CP_COMMIT() asm volatile("cp.async.commit_group;" ::: "memory")
#define CP_WAIT1()  asm volatile("cp.async.wait_group 1;" ::: "memory")

#define MMA_F16(d, a0, a1, a2, a3, b0, b1) \
    asm volatile("mma.sync.aligned.m16n8k16.row.col.f32.f16.f16.f32 " \
        "{%0,%1,%2,%3}, {%4,%5,%6,%7}, {%8,%9}, {%0,%1,%2,%3};" \
        : "+f"((d)[0]), "+f"((d)[1]), "+f"((d)[2]), "+f"((d)[3]) \
        : "r"(a0), "r"(a1), "r"(a2), "r"(a3), "r"(b0), "r"(b1))

enum { MODE_BIAS = 1, MODE_SUME = 3, MODE_SCALE = 5, MODE_RED = 7 };

// ---------------- fp16 mma.sync GEMM ----------------
// C[M x N] (+ per-blockIdx.z batch strides) = A[M x K] * B[N x K]^T.
// A, B: __half, stored with the within-16 K permutation (perm16).
// MODE_BIAS  (PR=1): C half perm16 cols, +bias. If blockIdx.z >= HEADS, the
//            second operand set (A2/B2/Cv2/bias2) is used with h = z - HEADS
//            (lets two equal-shape projection GEMMs share one launch).
// MODE_SUME  (PR=1): C half perm16 = exp(alpha*acc) via st.cs; colsum += col sums.
// MODE_SCALE (PR=1): C half perm16 = acc * csinv[h][c]   (colsum arg = csinv).
// MODE_RED   (PR=0): atomicAdd fp32 acc into C (split over blockIdx.z; sC = 0).
//            Additionally (wv != null): prologue writes the CTA's disjoint
//            wout strip wv[(h*NSENT+row)*MKNOW + m] = half(A[row][m]) * csinv[h][m]
//            for m in [blockIdx.x*512, +512), rows row0..row0+127.
template <int MODE, int PR>
__global__ void __launch_bounds__(256, 2)
hgemm_k(const __half* __restrict__ A, const __half* __restrict__ B, void* __restrict__ Cv,
        int Kn, int lda, int ldb, int ldc,
        long long sA, long long sB, long long sC,
        const float* __restrict__ bias, int sBias, float alpha,
        float* __restrict__ colsum, int sCol, float* __restrict__ wv,
        const __half* A2, const __half* B2, void* Cv2, const float* bias2)
{
    extern __shared__ char smem[];
    const uint32_t smem_b = smem_u32(smem);
    int h = blockIdx.z;
    if (MODE == MODE_BIAS && h >= HEADS) {
        h -= HEADS;
        A = A2; B = B2; Cv = Cv2; bias = bias2;
    }
    A += (long long)h * sA;
    B += (long long)h * sB;

    const int t = threadIdx.x;
    const int wid = t >> 5, lane = t & 31;
    const int lr = lane >> 2;    // 0..7
    const int lc = lane & 3;     // 0..3
    const int wm = (wid & 1) * 64;
    const int wn = (wid >> 1) * 32;
    const int row0 = blockIdx.y * BM;
    const int col0 = blockIdx.x * BN;
    const int nKT = Kn / BKH;

    // fill mapping: per operand 128 rows x 8 chunks(16B); 4 chunks/thread
    // smem slot of chunk o in row r: o ^ ((r&3)<<1)   (conflict-free swizzle)
#define LOAD_TILE(kt, s) do { \
    long long _k0 = (long long)(kt) * BKH; \
    uint32_t _sa = smem_b + (s) * STAGE_BYTES; \
    uint32_t _sb2 = _sa + TILE_BYTES_H; \
    _Pragma("unroll") \
    for (int _q = 0; _q < 4; _q++) { \
        int _ci = t + _q * 256; \
        int _r = _ci >> 3, _o = _ci & 7; \
        uint32_t _d = _r * 128 + (uint32_t)((_o ^ ((_r & 3) << 1)) << 4); \
        CP_ASYNC16(_sa + _d,  A + (long long)(row0 + _r) * lda + _k0 + _o * 8); \
        CP_ASYNC16(_sb2 + _d, B + (long long)(col0 + _r) * ldb + _k0 + _o * 8); \
    } \
} while (0)

    float acc[4][4][4];
#pragma unroll
    for (int i = 0; i < 4; i++)
#pragma unroll
        for (int j = 0; j < 4; j++)
#pragma unroll
            for (int q = 0; q < 4; q++) acc[i][j][q] = 0.0f;

    LOAD_TILE(0, 0); CP_COMMIT();
    LOAD_TILE(1, 1); CP_COMMIT();

    // ---- fused weights-output writer (RED only): overlaps with cp.async fill ----
    if (MODE == MODE_RED && wv != nullptr) {
        const int m0 = col0 * 4;                 // x-tile covers 512 m's
        const float* ci = colsum + (long long)h * sCol + m0;
        float* wbase = wv + ((long long)h * NSENT + row0) * MKNOW + m0;
#pragma unroll 1
        for (int g = 0; g < 16; g++) {
            const int idx = (g << 8) + t;        // 0..4095
            const int r = idx >> 5;              // row 0..127
            const int gr = (idx & 31) << 4;      // m offset within strip: 0,16,..,496
            const __half* ep = A + (long long)(row0 + r) * lda + m0 + gr;
            __half e[16];
            *(uint4*)&e[0] = *(const uint4*)ep;
            *(uint4*)&e[8] = *(const uint4*)(ep + 8);
            float ci4[16];
#pragma unroll
            for (int q = 0; q < 4; q++)
                *(float4*)&ci4[q * 4] = *(const float4*)(ci + gr + q * 4);
            float o[16];
#pragma unroll
            for (int j2 = 0; j2 < 16; j2++)
                o[j2] = __half2float(e[perm16(j2)]) * ci4[j2];
            float* wp = wbase + (long long)r * MKNOW + gr;
#pragma unroll
            for (int q = 0; q < 4; q++)
                __stcs((float4*)(wp + q * 4),
                       make_float4(o[q*4], o[q*4+1], o[q*4+2], o[q*4+3]));
        }
    }

    const uint32_t sx = (uint32_t)((lr & 3) << 1);   // row&3 == lr&3 for all fragment rows
    const uint32_t inb = (uint32_t)((lc & 1) * 8);   // byte within 16B chunk
    const uint32_t ch0 = (uint32_t)(lc >> 1);        // chunk within 32B k-group

    int sb = 0;  // = it % 3
    for (int it = 0; it < nKT; it++) {
        CP_WAIT1();
        __syncthreads();
        if (it + 2 < nKT) {
            int sl = sb + 2; if (sl >= STAGES) sl -= STAGES;
            LOAD_TILE(it + 2, sl);
        }
        CP_COMMIT();

        const char* As = smem + sb * STAGE_BYTES;
        const char* Bs = As + TILE_BYTES_H;
#pragma unroll
        for (int ks = 0; ks < 4; ks++) {
            const uint32_t aoff = (((ch0 + 2 * ks) ^ sx) << 4) + inb;
            uint2 al[4], ah[4], b[4];
#pragma unroll
            for (int i = 0; i < 4; i++) {
                const int ra = wm + i * 16 + lr;
                al[i] = *(const uint2*)(As + ra * 128 + aoff);
                ah[i] = *(const uint2*)(As + (ra + 8) * 128 + aoff);
            }
#pragma unroll
            for (int j = 0; j < 4; j++) {
                const int rb = wn + j * 8 + lr;
                b[j] = *(const uint2*)(Bs + rb * 128 + aoff);
            }
#pragma unroll
            for (int i = 0; i < 4; i++)
#pragma unroll
                for (int j = 0; j < 4; j++)
                    MMA_F16(acc[i][j], al[i].x, ah[i].x, al[i].y, ah[i].y, b[j].x, b[j].y);
        }
        sb++; if (sb == STAGES) sb = 0;
    }

    // epilogue
    const long long co = (long long)h * sC;
    float*  Cf = (float*)Cv + co;
    __half* Ch = (__half*)Cv + co;
#pragma unroll
    for (int j = 0; j < 4; j++) {
        const int c = col0 + wn + j * 8 + lc * 2;
        float b0 = 0.0f, b1 = 0.0f;
        if (MODE == MODE_BIAS) {
            b0 = bias[(long long)h * sBias + c];
            b1 = bias[(long long)h * sBias + c + 1];
        }
        float inv0 = 0.0f, inv1 = 0.0f;
        if (MODE == MODE_SCALE) {
            inv0 = colsum[(long long)h * sCol + c];       // csinv
            inv1 = colsum[(long long)h * sCol + c + 1];
        }
        float s0 = 0.0f, s1 = 0.0f;
#pragma unroll
        for (int i = 0; i < 4; i++) {
            const int r = row0 + wm + i * 16 + lr;
            float d0 = acc[i][j][0], d1 = acc[i][j][1];
            float d2 = acc[i][j][2], d3 = acc[i][j][3];
            if (MODE == MODE_SUME) {
                d0 = __expf(d0 * alpha); d1 = __expf(d1 * alpha);
                d2 = __expf(d2 * alpha); d3 = __expf(d3 * alpha);
                s0 += d0 + d2; s1 += d1 + d3;
            } else if (MODE == MODE_SCALE) {
                d0 *= inv0; d1 *= inv1; d2 *= inv0; d3 *= inv1;
            } else if (MODE == MODE_BIAS) {
                d0 += b0; d1 += b1; d2 += b0; d3 += b1;
            }
            if (MODE == MODE_RED) {
                atomicAdd(&Cf[(long long)r * ldc + c],           d0);
                atomicAdd(&Cf[(long long)r * ldc + c + 1],       d1);
                atomicAdd(&Cf[(long long)(r + 8) * ldc + c],     d2);
                atomicAdd(&Cf[(long long)(r + 8) * ldc + c + 1], d3);
            } else if (MODE == MODE_SUME) {
                // E is 268MB, re-read only much later -> streaming stores
                const int pc = perm16(c);
                stcs_h2(&Ch[(long long)r * ldc + pc],       __floats2half2_rn(d0, d1));
                stcs_h2(&Ch[(long long)(r + 8) * ldc + pc], __floats2half2_rn(d2, d3));
            } else {   // PR=1 half perm16 store (cached; soon re-read)
                const int pc = perm16(c);   // c even -> perm16(c+1) == pc+1
                *(__half2*)&Ch[(long long)r * ldc + pc] = __floats2half2_rn(d0, d1);
                *(__half2*)&Ch[(long long)(r + 8) * ldc + pc] = __floats2half2_rn(d2, d3);
            }
        }
        if (MODE == MODE_SUME) {
#pragma unroll
            for (int msk = 4; msk <= 16; msk <<= 1) {
                s0 += __shfl_xor_sync(0xFFFFFFFFu, s0, msk);
                s1 += __shfl_xor_sync(0xFFFFFFFFu, s1, msk);
            }
            if (lane < 4) {
                atomicAdd(&colsum[(long long)h * sCol + c], s0);
                atomicAdd(&colsum[(long long)h * sCol + c + 1], s1);
            }
        }
    }
}

// ---------------- prep / softmax kernels ----------------

// fp32 -> fp16 RN, within-16 perm, same layout. total % 16 == 0.
__global__ void converth_k(const float* __restrict__ in, __half* __restrict__ out,
                           long long total) {
    const long long ng = total >> 4;
    for (long long g = (long long)blockIdx.x * blockDim.x + threadIdx.x;
         g < ng; g += (long long)gridDim.x * blockDim.x) {
        const float* p = in + (g << 4);
        __half tmp[16];
#pragma unroll
        for (int j = 0; j < 16; j++) tmp[perm16(j)] = __float2half_rn(p[j]);
        *(uint4*)(out + (g << 4))     = *(uint4*)tmp;
        *(uint4*)(out + (g << 4) + 8) = *(uint4*)(tmp + 8);
    }
}

// fp32 [R,C] (+batch strides) -> half [C,R] RN-rounded, out-col perm16'd
__global__ void transposeh_k(const float* __restrict__ in, __half* __restrict__ out,
                             int R, int C, long long sIn, long long sOut) {
    __shared__ float tile[32][33];
    const int h = blockIdx.z;
    in += (long long)h * sIn;
    out += (long long)h * sOut;
    const int c0 = blockIdx.x * 32, r0 = blockIdx.y * 32;
    const int x = threadIdx.x, y = threadIdx.y;
#pragma unroll
    for (int j = 0; j < 32; j += 8)
        tile[y + j][x] = in[(long long)(r0 + y + j) * C + c0 + x];
    __syncthreads();
#pragma unroll
    for (int j = 0; j < 32; j += 8)
        out[(long long)(c0 + y + j) * R + r0 + perm16(x)] =
            __float2half_rn(tile[x][y + j]);
}

__global__ void csinv_k() {
    int i = blockIdx.x * blockDim.x + threadIdx.x;
    if (i < HEADS * MKNOW) g_csinv[i] = 1.0f / g_colsum[i];
}

// out0[n][e] = b_f[e] (pre-fill before split-K RED) + zero colsum in same pass
__global__ void initout_k(float* __restrict__ out0, const float* __restrict__ bf) {
    int i = blockIdx.x * blockDim.x + threadIdx.x;     // over 1M float4 groups
    if (i < NSENT * SENTD / 4) {
        int e = (i << 2) & (SENTD - 1);
        ((float4*)out0)[i] = *(const float4*)&bf[e];
    }
    if (i < HEADS * MKNOW / 4)
        ((float4*)g_colsum)[i] = make_float4(0.f, 0.f, 0.f, 0.f);
}

// ---------------- launch ----------------
extern "C" void kernel_launch(void* const* d_in, const int* in_sizes, int n_in,
                              void* d_out, int out_size)
{
    const float* sentences = (const float*)d_in[0];
    const float* knowledge = (const float*)d_in[1];
    const float* W_s = (const float*)d_in[2];
    const float* b_s = (const float*)d_in[3];
    const float* W_k = (const float*)d_in[4];
    const float* b_k = (const float*)d_in[5];
    const float* W_f = (const float*)d_in[6];
    const float* b_f = (const float*)d_in[7];

    float* out0 = (float*)d_out;                        // [4096,1024]
    float* wout = out0 + (long long)NSENT * SENTD;      // [8*4096,4096]

    __half* gSentH = nullptr; cudaGetSymbolAddress((void**)&gSentH, g_sentH);
    __half* gKnowH = nullptr; cudaGetSymbolAddress((void**)&gKnowH, g_knowH);
    __half* gWsT = nullptr;   cudaGetSymbolAddress((void**)&gWsT, g_WsTh);
    __half* gWkT = nullptr;   cudaGetSymbolAddress((void**)&gWkT, g_WkTh);
    __half* gSh = nullptr;    cudaGetSymbolAddress((void**)&gSh, g_Sh);
    __half* gKph = nullptr;   cudaGetSymbolAddress((void**)&gKph, g_Kph);
    __half* gWfT = nullptr;   cudaGetSymbolAddress((void**)&gWfT, g_WfTh);
    __half* gPT = nullptr;    cudaGetSymbolAddress((void**)&gPT, g_PTh);
    __half* gE = nullptr;     cudaGetSymbolAddress((void**)&gE, g_Eh);
    float* gCs = nullptr;     cudaGetSymbolAddress((void**)&gCs, g_colsum);
    float* gCi = nullptr;     cudaGetSymbolAddress((void**)&gCi, g_csinv);

    cudaFuncSetAttribute(hgemm_k<MODE_BIAS, 1>,  cudaFuncAttributeMaxDynamicSharedMemorySize, SMEM_BYTES);
    cudaFuncSetAttribute(hgemm_k<MODE_SUME, 1>,  cudaFuncAttributeMaxDynamicSharedMemorySize, SMEM_BYTES);
    cudaFuncSetAttribute(hgemm_k<MODE_SCALE, 1>, cudaFuncAttributeMaxDynamicSharedMemorySize, SMEM_BYTES);
    cudaFuncSetAttribute(hgemm_k<MODE_RED, 0>,   cudaFuncAttributeMaxDynamicSharedMemorySize, SMEM_BYTES);

    const float inv_sqrt_hd = 0.08838834764831845f;

    // --- prep: fp16 converts + transposes (all K-perm16'd) + out/colsum init ---
    converth_k<<<1024, 256>>>(sentences, gSentH, (long long)NSENT * SENTD);
    converth_k<<<1024, 256>>>(knowledge, gKnowH, (long long)MKNOW * SENTD);
    transposeh_k<<<dim3(HD / 32, SENTD / 32, HEADS), dim3(32, 8)>>>(
        W_s, gWsT, SENTD, HD, (long long)SENTD * HD, (long long)HD * SENTD);
    transposeh_k<<<dim3(HD / 32, SENTD / 32, HEADS), dim3(32, 8)>>>(
        W_k, gWkT, SENTD, HD, (long long)SENTD * HD, (long long)HD * SENTD);
    transposeh_k<<<dim3(SENTD / 32, (HEADS * SENTD) / 32, 1), dim3(32, 8)>>>(
        W_f, gWfT, HEADS * SENTD, SENTD, 0LL, 0LL);
    initout_k<<<(NSENT * SENTD / 4 + 255) / 256, 256>>>(out0, b_f);

    // --- projections (plain fp16, K=1024), both in ONE launch (z<8: S, z>=8: Kp) ---
    hgemm_k<MODE_BIAS, 1><<<dim3(1, NSENT / BM, 2 * HEADS), 256, SMEM_BYTES>>>(
        gSentH, gWsT, gSh, SENTD, SENTD, SENTD, HD,
        0LL, (long long)HD * SENTD, (long long)NSENT * HD, b_s, HD, 0.0f, nullptr, 0, nullptr,
        gKnowH, gWkT, gKph, b_k);

    // --- scores (K=128): E = exp(scores/sqrt(HD)) fp16 perm16 (st.cs) + fused colsum ---
    hgemm_k<MODE_SUME, 1><<<dim3(MKNOW / BN, NSENT / BM, HEADS), 256, SMEM_BYTES>>>(
        gSh, gKph, gE, HD, HD, HD, MKNOW,
        (long long)NSENT * HD, (long long)MKNOW * HD, (long long)NSENT * MKNOW,
        nullptr, 0, inv_sqrt_hd, gCs, MKNOW, nullptr,
        nullptr, nullptr, nullptr, nullptr);

    // --- reciprocal column sums ---
    csinv_k<<<(HEADS * MKNOW + 255) / 256, 256>>>();

    // --- PT'[h][e][m] = (sum_d Wf[h*1024+d][e] * know[m][d]) * csinv[h][m] ---
    hgemm_k<MODE_SCALE, 1><<<dim3(MKNOW / BN, SENTD / BM, HEADS), 256, SMEM_BYTES>>>(
        gWfT, gKnowH, gPT, SENTD, HEADS * SENTD, SENTD, MKNOW,
        (long long)SENTD, 0LL, (long long)SENTD * MKNOW, nullptr, 0, 0.0f, gCi, MKNOW, nullptr,
        nullptr, nullptr, nullptr, nullptr);

    // --- output: out0 += E[h] @ PT'[h]^T (split-K RED, bias pre-filled);
    //     fused prologue writes wout = fp16(E) * csinv, one disjoint strip per CTA ---
    hgemm_k<MODE_RED, 0><<<dim3(SENTD / BN, NSENT / BM, HEADS), 256, SMEM_BYTES>>>(
        gE, gPT, out0, MKNOW, MKNOW, MKNOW, SENTD,
        (long long)NSENT * MKNOW, (long long)SENTD * MKNOW, 0LL,
        nullptr, 0, 0.0f, gCi, MKNOW, wout,
        nullptr, nullptr, nullptr, nullptr);
}

// round 15
// speedup vs baseline: 1.1748x; 1.0076x over previous
#include <cuda_runtime.h>
#include <cuda_fp16.h>
#include <cstdint>
#include <math.h>

// ---------------- problem constants ----------------
#define NSENT 4096
#define MKNOW 4096
#define HEADS 8
#define SENTD 1024
#define HD    128

// ---------------- GEMM tile config ----------------
#define BM 128
#define BN 128
#define BKH 64                          // k halves per stage (4 mma k16 steps)
#define TILE_BYTES_H (128 * 128)        // 128 rows x 128B
#define STAGE_BYTES (2 * TILE_BYTES_H)  // A + B = 32 KB
#define STAGES 3
#define SMEM_BYTES (STAGES * STAGE_BYTES)   // 96 KB -> 2 CTAs/SM

// ---------------- scratch (static device arrays) ----------------
__device__ __half g_sentH[(size_t)NSENT*SENTD];
__device__ __half g_knowH[(size_t)MKNOW*SENTD];
__device__ __half g_WsTh[(size_t)HEADS*HD*SENTD];
__device__ __half g_WkTh[(size_t)HEADS*HD*SENTD];
__device__ __half g_Sh [(size_t)HEADS*NSENT*HD];
__device__ __half g_Kph[(size_t)HEADS*MKNOW*HD];
__device__ __half g_WfTh[(size_t)SENTD*HEADS*SENTD];
__device__ __half g_PTh[(size_t)HEADS*SENTD*MKNOW];     // PT'[h][e][m] = (know @ Wf_h)^T * csinv
__device__ __half g_Eh[(size_t)HEADS*NSENT*MKNOW];      // exp(scores) fp16 perm16, 268MB
__device__ float  g_colsum[HEADS*MKNOW];
__device__ float  g_csinv[HEADS*MKNOW];

// ---------------- helpers ----------------
__device__ __forceinline__ uint32_t smem_u32(const void* p) {
    uint32_t a;
    asm("{ .reg .u64 t; cvta.to.shared.u64 t, %1; cvt.u32.u64 %0, t; }" : "=r"(a) : "l"(p));
    return a;
}
// within-16 K permutation: k = 8b + 2c + r  ->  4c + 2b + r
__device__ __forceinline__ int perm16(int k) {
    return (k & ~15) | (((k >> 1) & 3) << 2) | (((k >> 3) & 1) << 1) | (k & 1);
}
// streaming (evict-first) store of a half2
__device__ __forceinline__ void stcs_h2(__half* p, __half2 v) {
    uint32_t u = *reinterpret_cast<uint32_t*>(&v);
    asm volatile("st.global.cs.b32 [%0], %1;" :: "l"(p), "r"(u) : "memory");
}
// vector global reduction: {p[0],p[1]} += {a,b}  (sm_90+, 8B-aligned p)
__device__ __forceinline__ void redg_v2(float* p, float a, float b) {
    asm volatile("red.global.add.v2.f32 [%0], {%1, %2};" :: "l"(p), "f"(a), "f"(b) : "memory");
}

#define CP_ASYNC16(dst, src) \
    asm volatile("cp.async.cg.shared.global [%0], [%1], 16;" :: "r"(dst), "l"(src) : "memory")
#define CP_COMMIT() asm volatile("cp.async.commit_group;" ::: "memory")
#define CP_WAIT1()  asm volatile("cp.async.wait_group 1;" ::: "memory")

#define MMA_F16(d, a0, a1, a2, a3, b0, b1) \
    asm volatile("mma.sync.aligned.m16n8k16.row.col.f32.f16.f16.f32 " \
        "{%0,%1,%2,%3}, {%4,%5,%6,%7}, {%8,%9}, {%0,%1,%2,%3};" \
        : "+f"((d)[0]), "+f"((d)[1]), "+f"((d)[2]), "+f"((d)[3]) \
        : "r"(a0), "r"(a1), "r"(a2), "r"(a3), "r"(b0), "r"(b1))

enum { MODE_BIAS = 1, MODE_SUME = 3, MODE_SCALE = 5, MODE_RED = 7 };

// ---------------- fp16 mma.sync GEMM ----------------
// C[M x N] (+ per-blockIdx.z batch strides) = A[M x K] * B[N x K]^T.
// A, B: __half, stored with the within-16 K permutation (perm16).
// MODE_BIAS  (PR=1): C half perm16 cols, +bias. If blockIdx.z >= HEADS, the
//            second operand set (A2/B2/Cv2/bias2) is used with h = z - HEADS.
// MODE_SUME  (PR=1): C half perm16 = exp(alpha*acc) via st.cs; colsum += col sums.
// MODE_SCALE (PR=1): C half perm16 = acc * csinv[h][c]   (colsum arg = csinv).
// MODE_RED   (PR=0): red.v2 fp32 acc into C (split over blockIdx.z; sC = 0).
//            Additionally (wv != null): prologue writes the CTA's disjoint
//            wout strip wv[(h*NSENT+row)*MKNOW + m] = half(A[row][m]) * csinv[h][m]
//            for m in [blockIdx.x*512, +512), rows row0..row0+127.
template <int MODE, int PR>
__global__ void __launch_bounds__(256, 2)
hgemm_k(const __half* __restrict__ A, const __half* __restrict__ B, void* __restrict__ Cv,
        int Kn, int lda, int ldb, int ldc,
        long long sA, long long sB, long long sC,
        const float* __restrict__ bias, int sBias, float alpha,
        float* __restrict__ colsum, int sCol, float* __restrict__ wv,
        const __half* A2, const __half* B2, void* Cv2, const float* bias2)
{
    extern __shared__ char smem[];
    const uint32_t smem_b = smem_u32(smem);
    int h = blockIdx.z;
    if (MODE == MODE_BIAS && h >= HEADS) {
        h -= HEADS;
        A = A2; B = B2; Cv = Cv2; bias = bias2;
    }
    A += (long long)h * sA;
    B += (long long)h * sB;

    const int t = threadIdx.x;
    const int wid = t >> 5, lane = t & 31;
    const int lr = lane >> 2;    // 0..7
    const int lc = lane & 3;     // 0..3
    const int wm = (wid & 1) * 64;
    const int wn = (wid >> 1) * 32;
    const int row0 = blockIdx.y * BM;
    const int col0 = blockIdx.x * BN;
    const int nKT = Kn / BKH;

    // fill mapping: per operand 128 rows x 8 chunks(16B); 4 chunks/thread
    // smem slot of chunk o in row r: o ^ ((r&3)<<1)   (conflict-free swizzle)
#define LOAD_TILE(kt, s) do { \
    long long _k0 = (long long)(kt) * BKH; \
    uint32_t _sa = smem_b + (s) * STAGE_BYTES; \
    uint32_t _sb2 = _sa + TILE_BYTES_H; \
    _Pragma("unroll") \
    for (int _q = 0; _q < 4; _q++) { \
        int _ci = t + _q * 256; \
        int _r = _ci >> 3, _o = _ci & 7; \
        uint32_t _d = _r * 128 + (uint32_t)((_o ^ ((_r & 3) << 1)) << 4); \
        CP_ASYNC16(_sa + _d,  A + (long long)(row0 + _r) * lda + _k0 + _o * 8); \
        CP_ASYNC16(_sb2 + _d, B + (long long)(col0 + _r) * ldb + _k0 + _o * 8); \
    } \
} while (0)

    float acc[4][4][4];
#pragma unroll
    for (int i = 0; i < 4; i++)
#pragma unroll
        for (int j = 0; j < 4; j++)
#pragma unroll
            for (int q = 0; q < 4; q++) acc[i][j][q] = 0.0f;

    LOAD_TILE(0, 0); CP_COMMIT();
    LOAD_TILE(1, 1); CP_COMMIT();

    // ---- fused weights-output writer (RED only): overlaps with cp.async fill ----
    if (MODE == MODE_RED && wv != nullptr) {
        const int m0 = col0 * 4;                 // x-tile covers 512 m's
        const float* ci = colsum + (long long)h * sCol + m0;
        float* wbase = wv + ((long long)h * NSENT + row0) * MKNOW + m0;
#pragma unroll 1
        for (int g = 0; g < 16; g++) {
            const int idx = (g << 8) + t;        // 0..4095
            const int r = idx >> 5;              // row 0..127
            const int gr = (idx & 31) << 4;      // m offset within strip: 0,16,..,496
            const __half* ep = A + (long long)(row0 + r) * lda + m0 + gr;
            __half e[16];
            *(uint4*)&e[0] = *(const uint4*)ep;
            *(uint4*)&e[8] = *(const uint4*)(ep + 8);
            float ci4[16];
#pragma unroll
            for (int q = 0; q < 4; q++)
                *(float4*)&ci4[q * 4] = *(const float4*)(ci + gr + q * 4);
            float o[16];
#pragma unroll
            for (int j2 = 0; j2 < 16; j2++)
                o[j2] = __half2float(e[perm16(j2)]) * ci4[j2];
            float* wp = wbase + (long long)r * MKNOW + gr;
#pragma unroll
            for (int q = 0; q < 4; q++)
                __stcs((float4*)(wp + q * 4),
                       make_float4(o[q*4], o[q*4+1], o[q*4+2], o[q*4+3]));
        }
    }

    const uint32_t sx = (uint32_t)((lr & 3) << 1);   // row&3 == lr&3 for all fragment rows
    const uint32_t inb = (uint32_t)((lc & 1) * 8);   // byte within 16B chunk
    const uint32_t ch0 = (uint32_t)(lc >> 1);        // chunk within 32B k-group

    int sb = 0;  // = it % 3
    for (int it = 0; it < nKT; it++) {
        CP_WAIT1();
        __syncthreads();
        if (it + 2 < nKT) {
            int sl = sb + 2; if (sl >= STAGES) sl -= STAGES;
            LOAD_TILE(it + 2, sl);
        }
        CP_COMMIT();

        const char* As = smem + sb * STAGE_BYTES;
        const char* Bs = As + TILE_BYTES_H;
#pragma unroll
        for (int ks = 0; ks < 4; ks++) {
            const uint32_t aoff = (((ch0 + 2 * ks) ^ sx) << 4) + inb;
            uint2 al[4], ah[4], b[4];
#pragma unroll
            for (int i = 0; i < 4; i++) {
                const int ra = wm + i * 16 + lr;
                al[i] = *(const uint2*)(As + ra * 128 + aoff);
                ah[i] = *(const uint2*)(As + (ra + 8) * 128 + aoff);
            }
#pragma unroll
            for (int j = 0; j < 4; j++) {
                const int rb = wn + j * 8 + lr;
                b[j] = *(const uint2*)(Bs + rb * 128 + aoff);
            }
#pragma unroll
            for (int i = 0; i < 4; i++)
#pragma unroll
                for (int j = 0; j < 4; j++)
                    MMA_F16(acc[i][j], al[i].x, ah[i].x, al[i].y, ah[i].y, b[j].x, b[j].y);
        }
        sb++; if (sb == STAGES) sb = 0;
    }

    // epilogue
    const long long co = (long long)h * sC;
    float*  Cf = (float*)Cv + co;
    __half* Ch = (__half*)Cv + co;
#pragma unroll
    for (int j = 0; j < 4; j++) {
        const int c = col0 + wn + j * 8 + lc * 2;
        float b0 = 0.0f, b1 = 0.0f;
        if (MODE == MODE_BIAS) {
            b0 = bias[(long long)h * sBias + c];
            b1 = bias[(long long)h * sBias + c + 1];
        }
        float inv0 = 0.0f, inv1 = 0.0f;
        if (MODE == MODE_SCALE) {
            inv0 = colsum[(long long)h * sCol + c];       // csinv
            inv1 = colsum[(long long)h * sCol + c + 1];
        }
        float s0 = 0.0f, s1 = 0.0f;
#pragma unroll
        for (int i = 0; i < 4; i++) {
            const int r = row0 + wm + i * 16 + lr;
            float d0 = acc[i][j][0], d1 = acc[i][j][1];
            float d2 = acc[i][j][2], d3 = acc[i][j][3];
            if (MODE == MODE_SUME) {
                d0 = __expf(d0 * alpha); d1 = __expf(d1 * alpha);
                d2 = __expf(d2 * alpha); d3 = __expf(d3 * alpha);
                s0 += d0 + d2; s1 += d1 + d3;
            } else if (MODE == MODE_SCALE) {
                d0 *= inv0; d1 *= inv1; d2 *= inv0; d3 *= inv1;
            } else if (MODE == MODE_BIAS) {
                d0 += b0; d1 += b1; d2 += b0; d3 += b1;
            }
            if (MODE == MODE_RED) {
                redg_v2(&Cf[(long long)r * ldc + c],       d0, d1);
                redg_v2(&Cf[(long long)(r + 8) * ldc + c], d2, d3);
            } else if (MODE == MODE_SUME) {
                // E is 268MB, re-read only much later -> streaming stores
                const int pc = perm16(c);
                stcs_h2(&Ch[(long long)r * ldc + pc],       __floats2half2_rn(d0, d1));
                stcs_h2(&Ch[(long long)(r + 8) * ldc + pc], __floats2half2_rn(d2, d3));
            } else {   // PR=1 half perm16 store (cached; soon re-read)
                const int pc = perm16(c);   // c even -> perm16(c+1) == pc+1
                *(__half2*)&Ch[(long long)r * ldc + pc] = __floats2half2_rn(d0, d1);
                *(__half2*)&Ch[(long long)(r + 8) * ldc + pc] = __floats2half2_rn(d2, d3);
            }
        }
        if (MODE == MODE_SUME) {
#pragma unroll
            for (int msk = 4; msk <= 16; msk <<= 1) {
                s0 += __shfl_xor_sync(0xFFFFFFFFu, s0, msk);
                s1 += __shfl_xor_sync(0xFFFFFFFFu, s1, msk);
            }
            if (lane < 4) {
                atomicAdd(&colsum[(long long)h * sCol + c], s0);
                atomicAdd(&colsum[(long long)h * sCol + c + 1], s1);
            }
        }
    }
}

// ---------------- prep / softmax kernels ----------------

// fused fp32 -> fp16 RN convert of TWO arrays (each totalA/totalB % 16 == 0),
// within-16 perm, same layout.
__global__ void converth2_k(const float* __restrict__ inA, __half* __restrict__ outA,
                            long long totalA,
                            const float* __restrict__ inB, __half* __restrict__ outB,
                            long long totalB) {
    const long long ngA = totalA >> 4;
    const long long ng = ngA + (totalB >> 4);
    for (long long g = (long long)blockIdx.x * blockDim.x + threadIdx.x;
         g < ng; g += (long long)gridDim.x * blockDim.x) {
        const float* p;
        __half* o;
        long long gg;
        if (g < ngA) { p = inA + (g << 4); o = outA + (g << 4); gg = g; }
        else { gg = g - ngA; p = inB + (gg << 4); o = outB + (gg << 4); }
        __half tmp[16];
#pragma unroll
        for (int j = 0; j < 16; j++) tmp[perm16(j)] = __float2half_rn(p[j]);
        *(uint4*)o       = *(uint4*)tmp;
        *(uint4*)(o + 8) = *(uint4*)(tmp + 8);
    }
}

// fp32 [R,C] (+batch strides) -> half [C,R] RN-rounded, out-col perm16'd.
// If in2 != null and blockIdx.z >= zSplit, switch to (in2, out2) with h -= zSplit.
__global__ void transposeh_k(const float* __restrict__ in, __half* __restrict__ out,
                             int R, int C, long long sIn, long long sOut,
                             const float* in2, __half* out2, int zSplit) {
    __shared__ float tile[32][33];
    int h = blockIdx.z;
    if (in2 != nullptr && h >= zSplit) {
        h -= zSplit;
        in = in2; out = out2;
    }
    in += (long long)h * sIn;
    out += (long long)h * sOut;
    const int c0 = blockIdx.x * 32, r0 = blockIdx.y * 32;
    const int x = threadIdx.x, y = threadIdx.y;
#pragma unroll
    for (int j = 0; j < 32; j += 8)
        tile[y + j][x] = in[(long long)(r0 + y + j) * C + c0 + x];
    __syncthreads();
#pragma unroll
    for (int j = 0; j < 32; j += 8)
        out[(long long)(c0 + y + j) * R + r0 + perm16(x)] =
            __float2half_rn(tile[x][y + j]);
}

__global__ void csinv_k() {
    int i = blockIdx.x * blockDim.x + threadIdx.x;
    if (i < HEADS * MKNOW) g_csinv[i] = 1.0f / g_colsum[i];
}

// out0[n][e] = b_f[e] (pre-fill before split-K RED) + zero colsum in same pass
__global__ void initout_k(float* __restrict__ out0, const float* __restrict__ bf) {
    int i = blockIdx.x * blockDim.x + threadIdx.x;     // over 1M float4 groups
    if (i < NSENT * SENTD / 4) {
        int e = (i << 2) & (SENTD - 1);
        ((float4*)out0)[i] = *(const float4*)&bf[e];
    }
    if (i < HEADS * MKNOW / 4)
        ((float4*)g_colsum)[i] = make_float4(0.f, 0.f, 0.f, 0.f);
}

// ---------------- launch ----------------
extern "C" void kernel_launch(void* const* d_in, const int* in_sizes, int n_in,
                              void* d_out, int out_size)
{
    const float* sentences = (const float*)d_in[0];
    const float* knowledge = (const float*)d_in[1];
    const float* W_s = (const float*)d_in[2];
    const float* b_s = (const float*)d_in[3];
    const float* W_k = (const float*)d_in[4];
    const float* b_k = (const float*)d_in[5];
    const float* W_f = (const float*)d_in[6];
    const float* b_f = (const float*)d_in[7];

    float* out0 = (float*)d_out;                        // [4096,1024]
    float* wout = out0 + (long long)NSENT * SENTD;      // [8*4096,4096]

    __half* gSentH = nullptr; cudaGetSymbolAddress((void**)&gSentH, g_sentH);
    __half* gKnowH = nullptr; cudaGetSymbolAddress((void**)&gKnowH, g_knowH);
    __half* gWsT = nullptr;   cudaGetSymbolAddress((void**)&gWsT, g_WsTh);
    __half* gWkT = nullptr;   cudaGetSymbolAddress((void**)&gWkT, g_WkTh);
    __half* gSh = nullptr;    cudaGetSymbolAddress((void**)&gSh, g_Sh);
    __half* gKph = nullptr;   cudaGetSymbolAddress((void**)&gKph, g_Kph);
    __half* gWfT = nullptr;   cudaGetSymbolAddress((void**)&gWfT, g_WfTh);
    __half* gPT = nullptr;    cudaGetSymbolAddress((void**)&gPT, g_PTh);
    __half* gE = nullptr;     cudaGetSymbolAddress((void**)&gE, g_Eh);
    float* gCs = nullptr;     cudaGetSymbolAddress((void**)&gCs, g_colsum);
    float* gCi = nullptr;     cudaGetSymbolAddress((void**)&gCi, g_csinv);

    cudaFuncSetAttribute(hgemm_k<MODE_BIAS, 1>,  cudaFuncAttributeMaxDynamicSharedMemorySize, SMEM_BYTES);
    cudaFuncSetAttribute(hgemm_k<MODE_SUME, 1>,  cudaFuncAttributeMaxDynamicSharedMemorySize, SMEM_BYTES);
    cudaFuncSetAttribute(hgemm_k<MODE_SCALE, 1>, cudaFuncAttributeMaxDynamicSharedMemorySize, SMEM_BYTES);
    cudaFuncSetAttribute(hgemm_k<MODE_RED, 0>,   cudaFuncAttributeMaxDynamicSharedMemorySize, SMEM_BYTES);

    const float inv_sqrt_hd = 0.08838834764831845f;

    // --- prep: fused fp16 converts + batched transposes + out/colsum init ---
    converth2_k<<<1024, 256>>>(sentences, gSentH, (long long)NSENT * SENTD,
                               knowledge, gKnowH, (long long)MKNOW * SENTD);
    transposeh_k<<<dim3(HD / 32, SENTD / 32, 2 * HEADS), dim3(32, 8)>>>(
        W_s, gWsT, SENTD, HD, (long long)SENTD * HD, (long long)HD * SENTD,
        W_k, gWkT, HEADS);
    transposeh_k<<<dim3(SENTD / 32, (HEADS * SENTD) / 32, 1), dim3(32, 8)>>>(
        W_f, gWfT, HEADS * SENTD, SENTD, 0LL, 0LL, nullptr, nullptr, 1);
    initout_k<<<(NSENT * SENTD / 4 + 255) / 256, 256>>>(out0, b_f);

    // --- projections (plain fp16, K=1024), both in ONE launch (z<8: S, z>=8: Kp) ---
    hgemm_k<MODE_BIAS, 1><<<dim3(1, NSENT / BM, 2 * HEADS), 256, SMEM_BYTES>>>(
        gSentH, gWsT, gSh, SENTD, SENTD, SENTD, HD,
        0LL, (long long)HD * SENTD, (long long)NSENT * HD, b_s, HD, 0.0f, nullptr, 0, nullptr,
        gKnowH, gWkT, gKph, b_k);

    // --- scores (K=128): E = exp(scores/sqrt(HD)) fp16 perm16 (st.cs) + fused colsum ---
    hgemm_k<MODE_SUME, 1><<<dim3(MKNOW / BN, NSENT / BM, HEADS), 256, SMEM_BYTES>>>(
        gSh, gKph, gE, HD, HD, HD, MKNOW,
        (long long)NSENT * HD, (long long)MKNOW * HD, (long long)NSENT * MKNOW,
        nullptr, 0, inv_sqrt_hd, gCs, MKNOW, nullptr,
        nullptr, nullptr, nullptr, nullptr);

    // --- reciprocal column sums ---
    csinv_k<<<(HEADS * MKNOW + 255) / 256, 256>>>();

    // --- PT'[h][e][m] = (sum_d Wf[h*1024+d][e] * know[m][d]) * csinv[h][m] ---
    hgemm_k<MODE_SCALE, 1><<<dim3(MKNOW / BN, SENTD / BM, HEADS), 256, SMEM_BYTES>>>(
        gWfT, gKnowH, gPT, SENTD, HEADS * SENTD, SENTD, MKNOW,
        (long long)SENTD, 0LL, (long long)SENTD * MKNOW, nullptr, 0, 0.0f, gCi, MKNOW, nullptr,
        nullptr, nullptr, nullptr, nullptr);

    // --- output: out0 += E[h] @ PT'[h]^T (split-K v2-RED, bias pre-filled);
    //     fused prologue writes wout = fp16(E) * csinv, one disjoint strip per CTA ---
    hgemm_k<MODE_RED, 0><<<dim3(SENTD / BN, NSENT / BM, HEADS), 256, SMEM_BYTES>>>(
        gE, gPT, out0, MKNOW, MKNOW, MKNOW, SENTD,
        (long long)NSENT * MKNOW, (long long)SENTD * MKNOW, 0LL,
        nullptr, 0, 0.0f, gCi, MKNOW, wout,
        nullptr, nullptr, nullptr, nullptr);
}

// round 17
// speedup vs baseline: 1.1766x; 1.0015x over previous
#include <cuda_runtime.h>
#include <cuda_fp16.h>
#include <cstdint>
#include <math.h>

// ---------------- problem constants ----------------
#define NSENT 4096
#define MKNOW 4096
#define HEADS 8
#define SENTD 1024
#define HD    128

// ---------------- GEMM tile config ----------------
#define BM 128
#define BN 128
#define BKH 64                          // k halves per stage (4 mma k16 steps)
#define TILE_BYTES_H (128 * 128)        // 128 rows x 128B
#define STAGE_BYTES (2 * TILE_BYTES_H)  // A + B = 32 KB
#define STAGES 3
#define SMEM_BYTES (STAGES * STAGE_BYTES)   // 96 KB -> 2 CTAs/SM

// ---------------- scratch (static device arrays) ----------------
__device__ __half g_sentH[(size_t)NSENT*SENTD];
__device__ __half g_knowH[(size_t)MKNOW*SENTD];
__device__ __half g_WsTh[(size_t)HEADS*HD*SENTD];
__device__ __half g_WkTh[(size_t)HEADS*HD*SENTD];
__device__ __half g_Sh [(size_t)HEADS*NSENT*HD];
__device__ __half g_Kph[(size_t)HEADS*MKNOW*HD];
__device__ __half g_WfTh[(size_t)SENTD*HEADS*SENTD];
__device__ __half g_PTh[(size_t)HEADS*SENTD*MKNOW];     // PT'[h][e][m] = (know @ Wf_h)^T * csinv
__device__ __half g_Eh[(size_t)HEADS*NSENT*MKNOW];      // exp(scores) fp16 perm16, 268MB
__device__ float  g_colsum[HEADS*MKNOW];
__device__ float  g_csinv[HEADS*MKNOW];                 // written by SCALE y==0 CTAs

// ---------------- helpers ----------------
__device__ __forceinline__ uint32_t smem_u32(const void* p) {
    uint32_t a;
    asm("{ .reg .u64 t; cvta.to.shared.u64 t, %1; cvt.u32.u64 %0, t; }" : "=r"(a) : "l"(p));
    return a;
}
// within-16 K permutation: k = 8b + 2c + r  ->  4c + 2b + r
__device__ __forceinline__ int perm16(int k) {
    return (k & ~15) | (((k >> 1) & 3) << 2) | (((k >> 3) & 1) << 1) | (k & 1);
}
// streaming (evict-first) store of a half2
__device__ __forceinline__ void stcs_h2(__half* p, __half2 v) {
    uint32_t u = *reinterpret_cast<uint32_t*>(&v);
    asm volatile("st.global.cs.b32 [%0], %1;" :: "l"(p), "r"(u) : "memory");
}
// vector global reduction: {p[0],p[1]} += {a,b}  (sm_90+, 8B-aligned p)
__device__ __forceinline__ void redg_v2(float* p, float a, float b) {
    asm volatile("red.global.add.v2.f32 [%0], {%1, %2};" :: "l"(p), "f"(a), "f"(b) : "memory");
}
// correctly-rounded fp32 reciprocal (immune to fast-math lowering)
__device__ __forceinline__ float rcp_rn(float x) {
    float r;
    asm("rcp.rn.f32 %0, %1;" : "=f"(r) : "f"(x));
    return r;
}

#define CP_ASYNC16(dst, src) \
    asm volatile("cp.async.cg.shared.global [%0], [%1], 16;" :: "r"(dst), "l"(src) : "memory")
#define CP_COMMIT() asm volatile("cp.async.commit_group;" ::: "memory")
#define CP_WAIT1()  asm volatile("cp.async.wait_group 1;" ::: "memory")

#define MMA_F16(d, a0, a1, a2, a3, b0, b1) \
    asm volatile("mma.sync.aligned.m16n8k16.row.col.f32.f16.f16.f32 " \
        "{%0,%1,%2,%3}, {%4,%5,%6,%7}, {%8,%9}, {%0,%1,%2,%3};" \
        : "+f"((d)[0]), "+f"((d)[1]), "+f"((d)[2]), "+f"((d)[3]) \
        : "r"(a0), "r"(a1), "r"(a2), "r"(a3), "r"(b0), "r"(b1))

enum { MODE_BIAS = 1, MODE_SUME = 3, MODE_SCALE = 5, MODE_RED = 7 };

// ---------------- fp16 mma.sync GEMM ----------------
// C[M x N] (+ per-blockIdx.z batch strides) = A[M x K] * B[N x K]^T.
// A, B: __half, stored with the within-16 K permutation (perm16).
// MODE_BIAS  (PR=1): C half perm16 cols, +bias. If blockIdx.z >= HEADS, the
//            second operand set (A2/B2/Cv2/bias2) is used with h = z - HEADS.
// MODE_SUME  (PR=1): C half perm16 = exp(alpha*acc) via st.cs; colsum += col sums.
// MODE_SCALE (PR=1): C half perm16 = acc * rcp(colsum[h][c]). y==0 CTAs also
//            side-store the reciprocals into wv (the csinv array).
// MODE_RED   (PR=0): red.v2 fp32 acc into C (split over blockIdx.z; sC = 0).
//            Additionally (wv != null): prologue writes the CTA's disjoint
//            wout strip: wv[(h*NSENT+row)*MKNOW + m] =
//            half(A[row][m]) * csinv[h][m], m in [blockIdx.x*512, +512).
template <int MODE, int PR>
__global__ void __launch_bounds__(256, 2)
hgemm_k(const __half* __restrict__ A, const __half* __restrict__ B, void* __restrict__ Cv,
        int Kn, int lda, int ldb, int ldc,
        long long sA, long long sB, long long sC,
        const float* __restrict__ bias, int sBias, float alpha,
        float* __restrict__ colsum, int sCol, float* __restrict__ wv,
        const __half* A2, const __half* B2, void* Cv2, const float* bias2)
{
    extern __shared__ char smem[];
    const uint32_t smem_b = smem_u32(smem);
    int h = blockIdx.z;
    if (MODE == MODE_BIAS && h >= HEADS) {
        h -= HEADS;
        A = A2; B = B2; Cv = Cv2; bias = bias2;
    }
    A += (long long)h * sA;
    B += (long long)h * sB;

    const int t = threadIdx.x;
    const int wid = t >> 5, lane = t & 31;
    const int lr = lane >> 2;    // 0..7
    const int lc = lane & 3;     // 0..3
    const int wm = (wid & 1) * 64;
    const int wn = (wid >> 1) * 32;
    const int row0 = blockIdx.y * BM;
    const int col0 = blockIdx.x * BN;
    const int nKT = Kn / BKH;

    // fill mapping: per operand 128 rows x 8 chunks(16B); 4 chunks/thread
    // smem slot of chunk o in row r: o ^ ((r&3)<<1)   (conflict-free swizzle)
#define LOAD_TILE(kt, s) do { \
    long long _k0 = (long long)(kt) * BKH; \
    uint32_t _sa = smem_b + (s) * STAGE_BYTES; \
    uint32_t _sb2 = _sa + TILE_BYTES_H; \
    _Pragma("unroll") \
    for (int _q = 0; _q < 4; _q++) { \
        int _ci = t + _q * 256; \
        int _r = _ci >> 3, _o = _ci & 7; \
        uint32_t _d = _r * 128 + (uint32_t)((_o ^ ((_r & 3) << 1)) << 4); \
        CP_ASYNC16(_sa + _d,  A + (long long)(row0 + _r) * lda + _k0 + _o * 8); \
        CP_ASYNC16(_sb2 + _d, B + (long long)(col0 + _r) * ldb + _k0 + _o * 8); \
    } \
} while (0)

    float acc[4][4][4];
#pragma unroll
    for (int i = 0; i < 4; i++)
#pragma unroll
        for (int j = 0; j < 4; j++)
#pragma unroll
            for (int q = 0; q < 4; q++) acc[i][j][q] = 0.0f;

    LOAD_TILE(0, 0); CP_COMMIT();
    LOAD_TILE(1, 1); CP_COMMIT();

    // ---- fused weights-output writer (RED only): overlaps with cp.async fill ----
    if (MODE == MODE_RED && wv != nullptr) {
        const int m0 = col0 * 4;                 // x-tile covers 512 m's
        const float* ci = colsum + (long long)h * sCol + m0;   // csinv array here
        float* wbase = wv + ((long long)h * NSENT + row0) * MKNOW + m0;
#pragma unroll 1
        for (int g = 0; g < 16; g++) {
            const int idx = (g << 8) + t;        // 0..4095
            const int r = idx >> 5;              // row 0..127
            const int gr = (idx & 31) << 4;      // m offset within strip: 0,16,..,496
            const __half* ep = A + (long long)(row0 + r) * lda + m0 + gr;
            __half e[16];
            *(uint4*)&e[0] = *(const uint4*)ep;
            *(uint4*)&e[8] = *(const uint4*)(ep + 8);
            float ci4[16];
#pragma unroll
            for (int q = 0; q < 4; q++)
                *(float4*)&ci4[q * 4] = *(const float4*)(ci + gr + q * 4);
            float o[16];
#pragma unroll
            for (int j2 = 0; j2 < 16; j2++)
                o[j2] = __half2float(e[perm16(j2)]) * ci4[j2];
            float* wp = wbase + (long long)r * MKNOW + gr;
#pragma unroll
            for (int q = 0; q < 4; q++)
                __stcs((float4*)(wp + q * 4),
                       make_float4(o[q*4], o[q*4+1], o[q*4+2], o[q*4+3]));
        }
    }

    const uint32_t sx = (uint32_t)((lr & 3) << 1);   // row&3 == lr&3 for all fragment rows
    const uint32_t inb = (uint32_t)((lc & 1) * 8);   // byte within 16B chunk
    const uint32_t ch0 = (uint32_t)(lc >> 1);        // chunk within 32B k-group

    int sb = 0;  // = it % 3
    for (int it = 0; it < nKT; it++) {
        CP_WAIT1();
        __syncthreads();
        if (it + 2 < nKT) {
            int sl = sb + 2; if (sl >= STAGES) sl -= STAGES;
            LOAD_TILE(it + 2, sl);
        }
        CP_COMMIT();

        const char* As = smem + sb * STAGE_BYTES;
        const char* Bs = As + TILE_BYTES_H;
#pragma unroll
        for (int ks = 0; ks < 4; ks++) {
            const uint32_t aoff = (((ch0 + 2 * ks) ^ sx) << 4) + inb;
            uint2 al[4], ah[4], b[4];
#pragma unroll
            for (int i = 0; i < 4; i++) {
                const int ra = wm + i * 16 + lr;
                al[i] = *(const uint2*)(As + ra * 128 + aoff);
                ah[i] = *(const uint2*)(As + (ra + 8) * 128 + aoff);
            }
#pragma unroll
            for (int j = 0; j < 4; j++) {
                const int rb = wn + j * 8 + lr;
                b[j] = *(const uint2*)(Bs + rb * 128 + aoff);
            }
#pragma unroll
            for (int i = 0; i < 4; i++)
#pragma unroll
                for (int j = 0; j < 4; j++)
                    MMA_F16(acc[i][j], al[i].x, ah[i].x, al[i].y, ah[i].y, b[j].x, b[j].y);
        }
        sb++; if (sb == STAGES) sb = 0;
    }

    // epilogue
    const long long co = (long long)h * sC;
    float*  Cf = (float*)Cv + co;
    __half* Ch = (__half*)Cv + co;
#pragma unroll
    for (int j = 0; j < 4; j++) {
        const int c = col0 + wn + j * 8 + lc * 2;
        float b0 = 0.0f, b1 = 0.0f;
        if (MODE == MODE_BIAS) {
            b0 = bias[(long long)h * sBias + c];
            b1 = bias[(long long)h * sBias + c + 1];
        }
        float inv0 = 0.0f, inv1 = 0.0f;
        if (MODE == MODE_SCALE) {
            inv0 = rcp_rn(colsum[(long long)h * sCol + c]);
            inv1 = rcp_rn(colsum[(long long)h * sCol + c + 1]);
            // y==0 CTAs publish the reciprocals (each column exactly once:
            // (wid&1)==0 picks one wm group; lr==0 picks one row owner)
            if (blockIdx.y == 0 && (wid & 1) == 0 && lr == 0 && wv != nullptr) {
                wv[(long long)h * sCol + c]     = inv0;
                wv[(long long)h * sCol + c + 1] = inv1;
            }
        }
        float s0 = 0.0f, s1 = 0.0f;
#pragma unroll
        for (int i = 0; i < 4; i++) {
            const int r = row0 + wm + i * 16 + lr;
            float d0 = acc[i][j][0], d1 = acc[i][j][1];
            float d2 = acc[i][j][2], d3 = acc[i][j][3];
            if (MODE == MODE_SUME) {
                d0 = __expf(d0 * alpha); d1 = __expf(d1 * alpha);
                d2 = __expf(d2 * alpha); d3 = __expf(d3 * alpha);
                s0 += d0 + d2; s1 += d1 + d3;
            } else if (MODE == MODE_SCALE) {
                d0 *= inv0; d1 *= inv1; d2 *= inv0; d3 *= inv1;
            } else if (MODE == MODE_BIAS) {
                d0 += b0; d1 += b1; d2 += b0; d3 += b1;
            }
            if (MODE == MODE_RED) {
                redg_v2(&Cf[(long long)r * ldc + c],       d0, d1);
                redg_v2(&Cf[(long long)(r + 8) * ldc + c], d2, d3);
            } else if (MODE == MODE_SUME) {
                // E is 268MB, re-read only much later -> streaming stores
                const int pc = perm16(c);
                stcs_h2(&Ch[(long long)r * ldc + pc],       __floats2half2_rn(d0, d1));
                stcs_h2(&Ch[(long long)(r + 8) * ldc + pc], __floats2half2_rn(d2, d3));
            } else {   // PR=1 half perm16 store (cached; soon re-read)
                const int pc = perm16(c);   // c even -> perm16(c+1) == pc+1
                *(__half2*)&Ch[(long long)r * ldc + pc] = __floats2half2_rn(d0, d1);
                *(__half2*)&Ch[(long long)(r + 8) * ldc + pc] = __floats2half2_rn(d2, d3);
            }
        }
        if (MODE == MODE_SUME) {
#pragma unroll
            for (int msk = 4; msk <= 16; msk <<= 1) {
                s0 += __shfl_xor_sync(0xFFFFFFFFu, s0, msk);
                s1 += __shfl_xor_sync(0xFFFFFFFFu, s1, msk);
            }
            if (lane < 4) {
                atomicAdd(&colsum[(long long)h * sCol + c], s0);
                atomicAdd(&colsum[(long long)h * sCol + c + 1], s1);
            }
        }
    }
}

// ---------------- prep kernels ----------------

// fused fp32 -> fp16 RN convert of TWO arrays (each totalA/totalB % 16 == 0),
// within-16 perm, same layout.
__global__ void converth2_k(const float* __restrict__ inA, __half* __restrict__ outA,
                            long long totalA,
                            const float* __restrict__ inB, __half* __restrict__ outB,
                            long long totalB) {
    const long long ngA = totalA >> 4;
    const long long ng = ngA + (totalB >> 4);
    for (long long g = (long long)blockIdx.x * blockDim.x + threadIdx.x;
         g < ng; g += (long long)gridDim.x * blockDim.x) {
        const float* p;
        __half* o;
        long long gg;
        if (g < ngA) { p = inA + (g << 4); o = outA + (g << 4); gg = g; }
        else { gg = g - ngA; p = inB + (gg << 4); o = outB + (gg << 4); }
        __half tmp[16];
#pragma unroll
        for (int j = 0; j < 16; j++) tmp[perm16(j)] = __float2half_rn(p[j]);
        *(uint4*)o       = *(uint4*)tmp;
        *(uint4*)(o + 8) = *(uint4*)(tmp + 8);
    }
}

// fp32 [R,C] (+batch strides) -> half [C,R] RN-rounded, out-col perm16'd.
// If in2 != null and blockIdx.z >= zSplit, switch to (in2, out2) with h -= zSplit.
__global__ void transposeh_k(const float* __restrict__ in, __half* __restrict__ out,
                             int R, int C, long long sIn, long long sOut,
                             const float* in2, __half* out2, int zSplit) {
    __shared__ float tile[32][33];
    int h = blockIdx.z;
    if (in2 != nullptr && h >= zSplit) {
        h -= zSplit;
        in = in2; out = out2;
    }
    in += (long long)h * sIn;
    out += (long long)h * sOut;
    const int c0 = blockIdx.x * 32, r0 = blockIdx.y * 32;
    const int x = threadIdx.x, y = threadIdx.y;
#pragma unroll
    for (int j = 0; j < 32; j += 8)
        tile[y + j][x] = in[(long long)(r0 + y + j) * C + c0 + x];
    __syncthreads();
#pragma unroll
    for (int j = 0; j < 32; j += 8)
        out[(long long)(c0 + y + j) * R + r0 + perm16(x)] =
            __float2half_rn(tile[x][y + j]);
}

// out0[n][e] = b_f[e] (pre-fill before split-K RED) + zero colsum in same pass
__global__ void initout_k(float* __restrict__ out0, const float* __restrict__ bf) {
    int i = blockIdx.x * blockDim.x + threadIdx.x;     // over 1M float4 groups
    if (i < NSENT * SENTD / 4) {
        int e = (i << 2) & (SENTD - 1);
        ((float4*)out0)[i] = *(const float4*)&bf[e];
    }
    if (i < HEADS * MKNOW / 4)
        ((float4*)g_colsum)[i] = make_float4(0.f, 0.f, 0.f, 0.f);
}

// ---------------- launch ----------------
extern "C" void kernel_launch(void* const* d_in, const int* in_sizes, int n_in,
                              void* d_out, int out_size)
{
    const float* sentences = (const float*)d_in[0];
    const float* knowledge = (const float*)d_in[1];
    const float* W_s = (const float*)d_in[2];
    const float* b_s = (const float*)d_in[3];
    const float* W_k = (const float*)d_in[4];
    const float* b_k = (const float*)d_in[5];
    const float* W_f = (const float*)d_in[6];
    const float* b_f = (const float*)d_in[7];

    float* out0 = (float*)d_out;                        // [4096,1024]
    float* wout = out0 + (long long)NSENT * SENTD;      // [8*4096,4096]

    __half* gSentH = nullptr; cudaGetSymbolAddress((void**)&gSentH, g_sentH);
    __half* gKnowH = nullptr; cudaGetSymbolAddress((void**)&gKnowH, g_knowH);
    __half* gWsT = nullptr;   cudaGetSymbolAddress((void**)&gWsT, g_WsTh);
    __half* gWkT = nullptr;   cudaGetSymbolAddress((void**)&gWkT, g_WkTh);
    __half* gSh = nullptr;    cudaGetSymbolAddress((void**)&gSh, g_Sh);
    __half* gKph = nullptr;   cudaGetSymbolAddress((void**)&gKph, g_Kph);
    __half* gWfT = nullptr;   cudaGetSymbolAddress((void**)&gWfT, g_WfTh);
    __half* gPT = nullptr;    cudaGetSymbolAddress((void**)&gPT, g_PTh);
    __half* gE = nullptr;     cudaGetSymbolAddress((void**)&gE, g_Eh);
    float* gCs = nullptr;     cudaGetSymbolAddress((void**)&gCs, g_colsum);
    float* gCi = nullptr;     cudaGetSymbolAddress((void**)&gCi, g_csinv);

    cudaFuncSetAttribute(hgemm_k<MODE_BIAS, 1>,  cudaFuncAttributeMaxDynamicSharedMemorySize, SMEM_BYTES);
    cudaFuncSetAttribute(hgemm_k<MODE_SUME, 1>,  cudaFuncAttributeMaxDynamicSharedMemorySize, SMEM_BYTES);
    cudaFuncSetAttribute(hgemm_k<MODE_SCALE, 1>, cudaFuncAttributeMaxDynamicSharedMemorySize, SMEM_BYTES);
    cudaFuncSetAttribute(hgemm_k<MODE_RED, 0>,   cudaFuncAttributeMaxDynamicSharedMemorySize, SMEM_BYTES);

    const float inv_sqrt_hd = 0.08838834764831845f;

    // --- prep: fused fp16 converts + batched transposes + out/colsum init ---
    converth2_k<<<1024, 256>>>(sentences, gSentH, (long long)NSENT * SENTD,
                               knowledge, gKnowH, (long long)MKNOW * SENTD);
    transposeh_k<<<dim3(HD / 32, SENTD / 32, 2 * HEADS), dim3(32, 8)>>>(
        W_s, gWsT, SENTD, HD, (long long)SENTD * HD, (long long)HD * SENTD,
        W_k, gWkT, HEADS);
    transposeh_k<<<dim3(SENTD / 32, (HEADS * SENTD) / 32, 1), dim3(32, 8)>>>(
        W_f, gWfT, HEADS * SENTD, SENTD, 0LL, 0LL, nullptr, nullptr, 1);
    initout_k<<<(NSENT * SENTD / 4 + 255) / 256, 256>>>(out0, b_f);

    // --- projections (plain fp16, K=1024), both in ONE launch (z<8: S, z>=8: Kp) ---
    hgemm_k<MODE_BIAS, 1><<<dim3(1, NSENT / BM, 2 * HEADS), 256, SMEM_BYTES>>>(
        gSentH, gWsT, gSh, SENTD, SENTD, SENTD, HD,
        0LL, (long long)HD * SENTD, (long long)NSENT * HD, b_s, HD, 0.0f, nullptr, 0, nullptr,
        gKnowH, gWkT, gKph, b_k);

    // --- scores (K=128): E = exp(scores/sqrt(HD)) fp16 perm16 (st.cs) + fused colsum ---
    hgemm_k<MODE_SUME, 1><<<dim3(MKNOW / BN, NSENT / BM, HEADS), 256, SMEM_BYTES>>>(
        gSh, gKph, gE, HD, HD, HD, MKNOW,
        (long long)NSENT * HD, (long long)MKNOW * HD, (long long)NSENT * MKNOW,
        nullptr, 0, inv_sqrt_hd, gCs, MKNOW, nullptr,
        nullptr, nullptr, nullptr, nullptr);

    // --- PT'[h][e][m] = (sum_d Wf[h*1024+d][e] * know[m][d]) * rcp(colsum[h][m]);
    //     y==0 CTAs also publish csinv into g_csinv for the RED wout-writer ---
    hgemm_k<MODE_SCALE, 1><<<dim3(MKNOW / BN, SENTD / BM, HEADS), 256, SMEM_BYTES>>>(
        gWfT, gKnowH, gPT, SENTD, HEADS * SENTD, SENTD, MKNOW,
        (long long)SENTD, 0LL, (long long)SENTD * MKNOW, nullptr, 0, 0.0f, gCs, MKNOW, gCi,
        nullptr, nullptr, nullptr, nullptr);

    // --- output: out0 += E[h] @ PT'[h]^T (split-K v2-RED, bias pre-filled);
    //     fused prologue writes wout = fp16(E) * csinv, one disjoint strip per CTA ---
    hgemm_k<MODE_RED, 0><<<dim3(SENTD / BN, NSENT / BM, HEADS), 256, SMEM_BYTES>>>(
        gE, gPT, out0, MKNOW, MKNOW, MKNOW, SENTD,
        (long long)NSENT * MKNOW, (long long)SENTD * MKNOW, 0LL,
        nullptr, 0, 0.0f, gCi, MKNOW, wout,
        nullptr, nullptr, nullptr, nullptr);
}